// round 5
// baseline (speedup 1.0000x reference)
#include <cuda_runtime.h>
#include <cuda_bf16.h>
#include <math.h>
#include <stdint.h>

// Problem constants
#define BSZ 16
#define TT  500
#define EE  1024
#define VV  4000
#define LL  100
#define SS  201
#define GG  101
#define MM  (BSZ*TT)     // 8000
#define MPAD 8064        // 63*128
#define NPAD 4096        // 16*256
#define NEGF (-1e30f)

// Main GEMM tiling: block 128x256x32, 8 warps (2Mx4N), warp tile 64x64
#define BM 128
#define BN 256
#define BK 32
#define NST 4
#define STAGE_BYTES 24576    // A 8KB + B 16KB
#define KITERS (EE/BK)       // 32
#define NTILES (NPAD/BN)     // 16
#define KSPLIT 4
#define LPK (EE/KSPLIT)      // 256
#define LPKIT (LPK/BK)       // 8

// Scratch (device globals: allocation-free per harness rules)
__device__ __nv_bfloat16 g_hsb[(size_t)MPAD * EE];     // padded rows zero
__device__ __nv_bfloat16 g_Wtb[(size_t)NPAD * EE];     // W transposed [n][k], padded zero
__device__ __nv_bfloat16 g_Wg[(size_t)BSZ * 128 * EE]; // gathered W cols per batch
__device__ float g_bias_g[BSZ * 128];
__device__ float2 g_part[(size_t)MM * NTILES];         // per (row, ntile) (max, sumexp)
__device__ float g_lse[MM];
__device__ float g_lpp[(size_t)KSPLIT * MM * 128];     // lp-gemm K partials
__device__ float g_lp[(size_t)MM * GG];
__device__ float g_ll[BSZ];

// ---------------------------------------------------------------------------
__device__ __forceinline__ uint32_t smem_u32(const void* p) {
    uint32_t a;
    asm("{ .reg .u64 t; cvta.to.shared.u64 t, %1; cvt.u32.u64 %0, t; }" : "=r"(a) : "l"(p));
    return a;
}
__device__ __forceinline__ void cp16(uint32_t dst, const void* src) {
    asm volatile("cp.async.cg.shared.global [%0], [%1], 16;" :: "r"(dst), "l"(src));
}
// swizzled offset for (row, 16B-chunk c) in a [rows x 64B] tile
__device__ __forceinline__ uint32_t swz(int row, int c) {
    return (uint32_t)(row * 64 + ((c ^ ((row >> 1) & 3)) << 4));
}

// ---------------------------------------------------------------------------
// Conversion kernels
// ---------------------------------------------------------------------------
__global__ __launch_bounds__(256)
void conv_hs_kernel(const float* __restrict__ hs) {
    size_t i = ((size_t)blockIdx.x * 256 + threadIdx.x) * 4;
    if (i >= (size_t)MPAD * EE) return;
    size_t row = i >> 10;
    float4 v = make_float4(0.f, 0.f, 0.f, 0.f);
    if (row < MM) v = *(const float4*)(hs + i);
    __nv_bfloat162* dst = (__nv_bfloat162*)(g_hsb + i);
    dst[0] = __nv_bfloat162(__float2bfloat16(v.x), __float2bfloat16(v.y));
    dst[1] = __nv_bfloat162(__float2bfloat16(v.z), __float2bfloat16(v.w));
}

__global__ __launch_bounds__(256)
void conv_W_kernel(const float* __restrict__ W) {
    __shared__ float t[32][33];
    int n0 = blockIdx.x * 32;
    int k0 = blockIdx.y * 32;
    int tx = threadIdx.x;      // 0..31
    int ty = threadIdx.y;      // 0..7
#pragma unroll
    for (int j = 0; j < 32; j += 8)
        t[ty + j][tx] = W[(size_t)(k0 + ty + j) * VV + n0 + tx];
    __syncthreads();
#pragma unroll
    for (int j = 0; j < 32; j += 8)
        g_Wtb[(size_t)(n0 + ty + j) * EE + k0 + tx] = __float2bfloat16(t[tx][ty + j]);
}

__global__ __launch_bounds__(256)
void pad_W_kernel() {
    int i = blockIdx.x * 256 + threadIdx.x;
    if (i < (NPAD - VV) * EE)
        g_Wtb[(size_t)VV * EE + i] = __float2bfloat16(0.f);
}

// ---------------------------------------------------------------------------
// Gather per-batch label columns of W into compact [128][EE] matrices
// ---------------------------------------------------------------------------
__global__ __launch_bounds__(128)
void gather_cols_kernel(const int* __restrict__ ys, const float* __restrict__ bias) {
    const int b = blockIdx.x >> 7;
    const int s = blockIdx.x & 127;
    const int tid = threadIdx.x;
    int col = -1;
    if (s == 0) col = 0;
    else if (s < GG) {
        int y = ys[b * LL + s - 1];
        col = y < 0 ? 0 : y;
    }
    uint4 v = make_uint4(0, 0, 0, 0);
    if (col >= 0) v = *(const uint4*)(g_Wtb + (size_t)col * EE + tid * 8);
    *(uint4*)(g_Wg + ((size_t)(b * 128 + s)) * EE + tid * 8) = v;
    if (tid == 0) g_bias_g[b * 128 + s] = (col >= 0) ? bias[col] : 0.f;
}

// ---------------------------------------------------------------------------
// Main GEMM (bf16 mma.sync, 8 warps, block 128x256, warp tile 64x64)
// with fused per-block LSE partial epilogue.
// ---------------------------------------------------------------------------
__global__ __launch_bounds__(256, 2)
void gemm_lse_kernel(const float* __restrict__ bias) {
    extern __shared__ char dsm[];
    __shared__ float2 red[4][BM];

    const int tid = threadIdx.x;
    const int warp = tid >> 5, lane = tid & 31;
    const int wm = (warp & 1) * 64, wn = (warp >> 1) * 64;
    const int bx = blockIdx.x, by = blockIdx.y;
    const int row0 = by * BM, col0 = bx * BN;
    const uint32_t sbase = smem_u32(dsm);   // stage: A at 0 (8KB), B at 8192 (16KB)

    const __nv_bfloat16* srcA = g_hsb + ((size_t)row0 + tid) * EE;      // tid<128 only
    const __nv_bfloat16* srcB = g_Wtb + ((size_t)col0 + tid) * EE;      // all 256
    uint32_t dsw[4];
#pragma unroll
    for (int c = 0; c < 4; c++) dsw[c] = swz(tid, c);

    float acc[4][8][4];
#pragma unroll
    for (int mi = 0; mi < 4; mi++)
#pragma unroll
        for (int ni = 0; ni < 8; ni++)
#pragma unroll
            for (int r = 0; r < 4; r++) acc[mi][ni][r] = 0.f;

    // ldmatrix smem offsets (stage-relative)
    uint32_t aoff[2][4], boff[2][4];
#pragma unroll
    for (int kk = 0; kk < 2; kk++) {
#pragma unroll
        for (int mi = 0; mi < 4; mi++) {
            int r = wm + mi * 16 + (lane & 15);
            int c = kk * 2 + (lane >> 4);
            aoff[kk][mi] = sbase + swz(r, c);
        }
#pragma unroll
        for (int nj = 0; nj < 4; nj++) {
            int r = wn + nj * 16 + ((lane >> 4) << 3) + (lane & 7);
            int c = kk * 2 + ((lane >> 3) & 1);
            boff[kk][nj] = sbase + 8192 + swz(r, c);
        }
    }

#define LOAD_STAGE(st, kt) do { \
    uint32_t b_ = (uint32_t)(st) * STAGE_BYTES; \
    if (tid < 128) { \
        const __nv_bfloat16* a_ = srcA + (kt) * BK; \
        cp16(sbase + b_ + dsw[0], a_); \
        cp16(sbase + b_ + dsw[1], a_ + 8); \
        cp16(sbase + b_ + dsw[2], a_ + 16); \
        cp16(sbase + b_ + dsw[3], a_ + 24); \
    } \
    const __nv_bfloat16* w_ = srcB + (kt) * BK; \
    cp16(sbase + b_ + 8192 + dsw[0], w_); \
    cp16(sbase + b_ + 8192 + dsw[1], w_ + 8); \
    cp16(sbase + b_ + 8192 + dsw[2], w_ + 16); \
    cp16(sbase + b_ + 8192 + dsw[3], w_ + 24); \
    asm volatile("cp.async.commit_group;" ::: "memory"); \
} while (0)

    LOAD_STAGE(0, 0);
    LOAD_STAGE(1, 1);
    LOAD_STAGE(2, 2);

    for (int kt = 0; kt < KITERS; kt++) {
        const int st = kt & 3;
        if (kt < KITERS - 2)
            asm volatile("cp.async.wait_group 2;" ::: "memory");
        else if (kt == KITERS - 2)
            asm volatile("cp.async.wait_group 1;" ::: "memory");
        else
            asm volatile("cp.async.wait_group 0;" ::: "memory");
        __syncthreads();

        const uint32_t stb = (uint32_t)st * STAGE_BYTES;
#pragma unroll
        for (int kk = 0; kk < 2; kk++) {
            uint32_t af[4][4], bf[4][4];
#pragma unroll
            for (int mi = 0; mi < 4; mi++)
                asm volatile("ldmatrix.sync.aligned.m8n8.x4.shared.b16 {%0,%1,%2,%3}, [%4];"
                             : "=r"(af[mi][0]), "=r"(af[mi][1]), "=r"(af[mi][2]), "=r"(af[mi][3])
                             : "r"(aoff[kk][mi] + stb));
#pragma unroll
            for (int nj = 0; nj < 4; nj++)
                asm volatile("ldmatrix.sync.aligned.m8n8.x4.shared.b16 {%0,%1,%2,%3}, [%4];"
                             : "=r"(bf[nj][0]), "=r"(bf[nj][1]), "=r"(bf[nj][2]), "=r"(bf[nj][3])
                             : "r"(boff[kk][nj] + stb));
#pragma unroll
            for (int mi = 0; mi < 4; mi++)
#pragma unroll
                for (int ni = 0; ni < 8; ni++)
                    asm volatile(
                        "mma.sync.aligned.m16n8k16.row.col.f32.bf16.bf16.f32 "
                        "{%0,%1,%2,%3}, {%4,%5,%6,%7}, {%8,%9}, {%0,%1,%2,%3};"
                        : "+f"(acc[mi][ni][0]), "+f"(acc[mi][ni][1]),
                          "+f"(acc[mi][ni][2]), "+f"(acc[mi][ni][3])
                        : "r"(af[mi][0]), "r"(af[mi][1]), "r"(af[mi][2]), "r"(af[mi][3]),
                          "r"(bf[ni >> 1][(ni & 1) * 2]), "r"(bf[ni >> 1][(ni & 1) * 2 + 1]));
        }
        if (kt + 3 < KITERS) LOAD_STAGE((kt + 3) & 3, kt + 3);
    }
#undef LOAD_STAGE

    // Fused LSE epilogue: per-row (max, sumexp) over this warp's 64 cols
#pragma unroll
    for (int mi = 0; mi < 4; mi++) {
        float m1 = NEGF, s1 = 0.f, m2 = NEGF, s2 = 0.f;
#pragma unroll
        for (int ni = 0; ni < 8; ni++) {
            int gcol = col0 + wn + ni * 8 + 2 * (lane & 3);
            float b0 = 0.f, b1 = 0.f;
            bool ok = gcol < VV;
            if (ok) { float2 bv = *(const float2*)(bias + gcol); b0 = bv.x; b1 = bv.y; }
            float v;
            v = ok ? acc[mi][ni][0] + b0 : NEGF;
            if (v > m1) { s1 = s1 * __expf(m1 - v) + 1.f; m1 = v; } else s1 += __expf(v - m1);
            v = ok ? acc[mi][ni][1] + b1 : NEGF;
            if (v > m1) { s1 = s1 * __expf(m1 - v) + 1.f; m1 = v; } else s1 += __expf(v - m1);
            v = ok ? acc[mi][ni][2] + b0 : NEGF;
            if (v > m2) { s2 = s2 * __expf(m2 - v) + 1.f; m2 = v; } else s2 += __expf(v - m2);
            v = ok ? acc[mi][ni][3] + b1 : NEGF;
            if (v > m2) { s2 = s2 * __expf(m2 - v) + 1.f; m2 = v; } else s2 += __expf(v - m2);
        }
#pragma unroll
        for (int msk = 1; msk <= 2; msk <<= 1) {
            float om = __shfl_xor_sync(0xffffffffu, m1, msk);
            float os = __shfl_xor_sync(0xffffffffu, s1, msk);
            float M = fmaxf(m1, om);
            s1 = s1 * __expf(m1 - M) + os * __expf(om - M);
            m1 = M;
            om = __shfl_xor_sync(0xffffffffu, m2, msk);
            os = __shfl_xor_sync(0xffffffffu, s2, msk);
            M = fmaxf(m2, om);
            s2 = s2 * __expf(m2 - M) + os * __expf(om - M);
            m2 = M;
        }
        if ((lane & 3) == 0) {
            int r1 = wm + mi * 16 + (lane >> 2);
            red[warp >> 1][r1] = make_float2(m1, s1);
            red[warp >> 1][r1 + 8] = make_float2(m2, s2);
        }
    }
    __syncthreads();
    if (tid < BM) {
        float m = NEGF, s = 0.f;
#pragma unroll
        for (int j = 0; j < 4; j++) {
            float2 p = red[j][tid];
            float M = fmaxf(m, p.x);
            s = s * __expf(m - M) + p.y * __expf(p.x - M);
            m = M;
        }
        int grow = row0 + tid;
        if (grow < MM) g_part[(size_t)grow * NTILES + bx] = make_float2(m, s);
    }
}

// ---------------------------------------------------------------------------
// lp GEMM: per batch, [<=500 x 1024] x [1024 x 128(gathered)] with K split 4.
// 4 warps, block 128x128. Writes raw partial sums to g_lpp.
// ---------------------------------------------------------------------------
__global__ __launch_bounds__(128, 2)
void lp_gemm_kernel() {
    extern __shared__ char dsm[];

    const int tid = threadIdx.x;
    const int warp = tid >> 5, lane = tid & 31;
    const int wm = (warp & 1) * 64, wn = (warp >> 1) * 64;
    const int mt = blockIdx.x;         // 0..3
    const int ks = blockIdx.y;         // 0..3
    const int b  = blockIdx.z;         // 0..15
    const int row0 = b * TT + mt * 128;
    const int kb = ks * LPK;
    const uint32_t sbase = smem_u32(dsm);

    const __nv_bfloat16* srcA = g_hsb + ((size_t)row0 + tid) * EE + kb;
    const __nv_bfloat16* srcB = g_Wg + ((size_t)(b * 128) + tid) * EE + kb;
    uint32_t dsw[4];
#pragma unroll
    for (int c = 0; c < 4; c++) dsw[c] = swz(tid, c);

    float acc[4][8][4];
#pragma unroll
    for (int mi = 0; mi < 4; mi++)
#pragma unroll
        for (int ni = 0; ni < 8; ni++)
#pragma unroll
            for (int r = 0; r < 4; r++) acc[mi][ni][r] = 0.f;

    uint32_t aoff[2][4], boff[2][4];
#pragma unroll
    for (int kk = 0; kk < 2; kk++) {
#pragma unroll
        for (int mi = 0; mi < 4; mi++) {
            int r = wm + mi * 16 + (lane & 15);
            int c = kk * 2 + (lane >> 4);
            aoff[kk][mi] = sbase + swz(r, c);
        }
#pragma unroll
        for (int nj = 0; nj < 4; nj++) {
            int r = wn + nj * 16 + ((lane >> 4) << 3) + (lane & 7);
            int c = kk * 2 + ((lane >> 3) & 1);
            boff[kk][nj] = sbase + 8192 + swz(r, c);
        }
    }

#define LOAD_STAGE(st, kt) do { \
    uint32_t b_ = (uint32_t)(st) * 16384; \
    const __nv_bfloat16* a_ = srcA + (kt) * BK; \
    const __nv_bfloat16* w_ = srcB + (kt) * BK; \
    cp16(sbase + b_ + dsw[0], a_); \
    cp16(sbase + b_ + dsw[1], a_ + 8); \
    cp16(sbase + b_ + dsw[2], a_ + 16); \
    cp16(sbase + b_ + dsw[3], a_ + 24); \
    cp16(sbase + b_ + 8192 + dsw[0], w_); \
    cp16(sbase + b_ + 8192 + dsw[1], w_ + 8); \
    cp16(sbase + b_ + 8192 + dsw[2], w_ + 16); \
    cp16(sbase + b_ + 8192 + dsw[3], w_ + 24); \
    asm volatile("cp.async.commit_group;" ::: "memory"); \
} while (0)

    LOAD_STAGE(0, 0);
    LOAD_STAGE(1, 1);
    LOAD_STAGE(2, 2);

    for (int kt = 0; kt < LPKIT; kt++) {
        const int st = kt & 3;
        if (kt < LPKIT - 2)
            asm volatile("cp.async.wait_group 2;" ::: "memory");
        else if (kt == LPKIT - 2)
            asm volatile("cp.async.wait_group 1;" ::: "memory");
        else
            asm volatile("cp.async.wait_group 0;" ::: "memory");
        __syncthreads();

        const uint32_t stb = (uint32_t)st * 16384;
#pragma unroll
        for (int kk = 0; kk < 2; kk++) {
            uint32_t af[4][4], bf[4][4];
#pragma unroll
            for (int mi = 0; mi < 4; mi++)
                asm volatile("ldmatrix.sync.aligned.m8n8.x4.shared.b16 {%0,%1,%2,%3}, [%4];"
                             : "=r"(af[mi][0]), "=r"(af[mi][1]), "=r"(af[mi][2]), "=r"(af[mi][3])
                             : "r"(aoff[kk][mi] + stb));
#pragma unroll
            for (int nj = 0; nj < 4; nj++)
                asm volatile("ldmatrix.sync.aligned.m8n8.x4.shared.b16 {%0,%1,%2,%3}, [%4];"
                             : "=r"(bf[nj][0]), "=r"(bf[nj][1]), "=r"(bf[nj][2]), "=r"(bf[nj][3])
                             : "r"(boff[kk][nj] + stb));
#pragma unroll
            for (int mi = 0; mi < 4; mi++)
#pragma unroll
                for (int ni = 0; ni < 8; ni++)
                    asm volatile(
                        "mma.sync.aligned.m16n8k16.row.col.f32.bf16.bf16.f32 "
                        "{%0,%1,%2,%3}, {%4,%5,%6,%7}, {%8,%9}, {%0,%1,%2,%3};"
                        : "+f"(acc[mi][ni][0]), "+f"(acc[mi][ni][1]),
                          "+f"(acc[mi][ni][2]), "+f"(acc[mi][ni][3])
                        : "r"(af[mi][0]), "r"(af[mi][1]), "r"(af[mi][2]), "r"(af[mi][3]),
                          "r"(bf[ni >> 1][(ni & 1) * 2]), "r"(bf[ni >> 1][(ni & 1) * 2 + 1]));
        }
        if (kt + 3 < LPKIT) LOAD_STAGE((kt + 3) & 3, kt + 3);
    }
#undef LOAD_STAGE

#pragma unroll
    for (int mi = 0; mi < 4; mi++) {
        int lr1 = mt * 128 + wm + mi * 16 + (lane >> 2);
        int s = wn + 2 * (lane & 3);
#pragma unroll
        for (int ni = 0; ni < 8; ni++) {
            int sc = s + ni * 8;
            if (lr1 < TT) {
                int gr = b * TT + lr1;
                *(float2*)(g_lpp + ((size_t)ks * MM + gr) * 128 + sc) =
                    make_float2(acc[mi][ni][0], acc[mi][ni][1]);
            }
            if (lr1 + 8 < TT) {
                int gr = b * TT + lr1 + 8;
                *(float2*)(g_lpp + ((size_t)ks * MM + gr) * 128 + sc) =
                    make_float2(acc[mi][ni][2], acc[mi][ni][3]);
            }
        }
    }
}

// ---------------------------------------------------------------------------
// Reduce 16 LSE partials per row -> lse (one warp per row)
// ---------------------------------------------------------------------------
__global__ __launch_bounds__(256)
void lse_reduce_kernel() {
    int row = blockIdx.x * 8 + (threadIdx.x >> 5);
    int lane = threadIdx.x & 31;
    float m = NEGF, s = 0.f;
    if (lane < NTILES) {
        float2 p = g_part[(size_t)row * NTILES + lane];
        m = p.x; s = p.y;
    }
#pragma unroll
    for (int msk = 8; msk > 0; msk >>= 1) {
        float om = __shfl_xor_sync(0xffffffffu, m, msk);
        float os = __shfl_xor_sync(0xffffffffu, s, msk);
        float M = fmaxf(m, om);
        s = s * __expf(m - M) + os * __expf(om - M);
        m = M;
    }
    if (lane == 0) g_lse[row] = m + logf(s);
}

// ---------------------------------------------------------------------------
// Combine: lp = sum_k partials + bias - lse
// ---------------------------------------------------------------------------
__global__ __launch_bounds__(128)
void combine_kernel() {
    const int row = blockIdx.x;
    const int s = threadIdx.x;
    if (s >= GG) return;
    const int b = row / TT;
    float acc = 0.f;
#pragma unroll
    for (int ks = 0; ks < KSPLIT; ks++)
        acc += g_lpp[((size_t)ks * MM + row) * 128 + s];
    g_lp[(size_t)row * GG + s] = acc + g_bias_g[b * 128 + s] - g_lse[row];
}

// ---------------------------------------------------------------------------
// CTC forward DP, one block per batch element
// ---------------------------------------------------------------------------
__global__ __launch_bounds__(256)
void ctc_dp_kernel(const int* __restrict__ ys, const int* __restrict__ ilens,
                   const int* __restrict__ olens) {
    extern __shared__ float sm[];
    float* lps = sm;                     // [TT][GG]
    float* abuf = sm + TT * GG;          // [2][256]

    const int b = blockIdx.x;
    const int tid = threadIdx.x;
    const int s = tid;

    const float* src = g_lp + (size_t)b * TT * GG;
    for (int i = tid; i < TT * GG; i += blockDim.x) lps[i] = src[i];

    int g = 0;
    bool allow = false;
    if (s < SS && (s & 1)) {
        int l = s >> 1;
        g = 1 + l;
        int yr = ys[b * LL + l];
        int y = yr < 0 ? 0 : yr;
        int ypr = -1;
        if (l > 0) {
            int yp = ys[b * LL + l - 1];
            ypr = yp < 0 ? 0 : yp;
        }
        allow = (y != 0) && (y != ypr);
    }

    float* a0 = abuf;
    float* a1 = abuf + 256;
    a0[s] = (s == 0) ? lps[0] : ((s == 1) ? lps[1] : NEGF);
    __syncthreads();

    const int ilen = ilens[b];
    for (int t = 1; t < ilen; t++) {
        if (s < SS) {
            float v1 = a0[s];
            float v2 = (s >= 1) ? a0[s - 1] : NEGF;
            float v3 = (s >= 2 && allow) ? a0[s - 2] : NEGF;
            float m = fmaxf(v1, fmaxf(v2, v3));
            float sum = __expf(v1 - m) + __expf(v2 - m) + __expf(v3 - m);
            a1[s] = m + __logf(sum) + lps[t * GG + g];
        }
        __syncthreads();
        float* tmp = a0; a0 = a1; a1 = tmp;
    }

    if (tid == 0) {
        const int olen = olens[b];
        float va = a0[2 * olen];
        float vb = a0[2 * olen - 1];
        float m = fmaxf(va, vb);
        g_ll[b] = m + logf(expf(va - m) + expf(vb - m));
    }
}

__global__ void finalize_kernel(float* __restrict__ out) {
    if (threadIdx.x == 0) {
        float sum = 0.0f;
        for (int i = 0; i < BSZ; i++) sum += g_ll[i];
        out[0] = -sum / (float)BSZ;
    }
}

// ---------------------------------------------------------------------------
extern "C" void kernel_launch(void* const* d_in, const int* in_sizes, int n_in,
                              void* d_out, int out_size) {
    const float* hs    = (const float*)d_in[0];
    const float* W     = (const float*)d_in[1];
    const float* bias  = (const float*)d_in[2];
    const int*   ys    = (const int*)d_in[3];
    const int*   ilens = (const int*)d_in[4];
    const int*   olens = (const int*)d_in[5];
    float* out = (float*)d_out;

    conv_hs_kernel<<<(MPAD * EE) / 1024, 256>>>(hs);
    conv_W_kernel<<<dim3(VV / 32, EE / 32), dim3(32, 8)>>>(W);
    pad_W_kernel<<<((NPAD - VV) * EE + 255) / 256, 256>>>();
    gather_cols_kernel<<<BSZ * 128, 128>>>(ys, bias);

    const int gemm_smem = NST * STAGE_BYTES;   // 96 KB
    cudaFuncSetAttribute(gemm_lse_kernel,
                         cudaFuncAttributeMaxDynamicSharedMemorySize, gemm_smem);
    dim3 ggrid(NPAD / BN, MPAD / BM);    // 16 x 63
    gemm_lse_kernel<<<ggrid, 256, gemm_smem>>>(bias);

    lse_reduce_kernel<<<MM / 8, 256>>>();

    const int lp_smem = 4 * 16384;
    cudaFuncSetAttribute(lp_gemm_kernel,
                         cudaFuncAttributeMaxDynamicSharedMemorySize, lp_smem);
    lp_gemm_kernel<<<dim3(4, KSPLIT, BSZ), 128, lp_smem>>>();

    combine_kernel<<<MM, 128>>>();

    const int dp_smem = TT * GG * sizeof(float) + 2 * 256 * sizeof(float);
    cudaFuncSetAttribute(ctc_dp_kernel,
                         cudaFuncAttributeMaxDynamicSharedMemorySize, dp_smem);
    ctc_dp_kernel<<<BSZ, 256, dp_smem>>>(ys, ilens, olens);

    finalize_kernel<<<1, 32>>>(out);
}

// round 6
// speedup vs baseline: 1.7113x; 1.7113x over previous
#include <cuda_runtime.h>
#include <cuda_bf16.h>
#include <math.h>
#include <stdint.h>

// Problem constants
#define BSZ 16
#define TT  500
#define EE  1024
#define VV  4000
#define LL  100
#define SS  201
#define GG  101
#define MM  (BSZ*TT)     // 8000
#define MPAD 8064        // 63*128
#define NPAD 4096        // 32*128
#define NEGF (-1e30f)

// GEMM tiling (4 warps, warp tile 64x64) -- proven R4 config
#define BM 128
#define BN 128
#define BK 32
#define NST 4
#define KITERS (EE/BK)   // 32
#define NTILES (NPAD/BN) // 32
#define KSPLIT 4
#define LPK (EE/KSPLIT)  // 256
#define LPKIT (LPK/BK)   // 8

// Scratch (device globals: allocation-free per harness rules)
__device__ __nv_bfloat16 g_hsb[(size_t)MPAD * EE];
__device__ __nv_bfloat16 g_Wtb[(size_t)NPAD * EE];
__device__ __nv_bfloat16 g_Wg[(size_t)BSZ * 128 * EE];
__device__ float g_bias_g[BSZ * 128];
__device__ float2 g_part[(size_t)MM * NTILES];
__device__ float g_lpp[(size_t)KSPLIT * MM * 128];
__device__ float g_lp[(size_t)MM * GG];
__device__ float g_ll[BSZ];

// ---------------------------------------------------------------------------
__device__ __forceinline__ uint32_t smem_u32(const void* p) {
    uint32_t a;
    asm("{ .reg .u64 t; cvta.to.shared.u64 t, %1; cvt.u32.u64 %0, t; }" : "=r"(a) : "l"(p));
    return a;
}
__device__ __forceinline__ void cp16(uint32_t dst, const void* src) {
    asm volatile("cp.async.cg.shared.global [%0], [%1], 16;" :: "r"(dst), "l"(src));
}
__device__ __forceinline__ uint32_t swz(int row, int c) {
    return (uint32_t)(row * 64 + ((c ^ ((row >> 1) & 3)) << 4));
}

// ---------------------------------------------------------------------------
// Conversion kernels
// ---------------------------------------------------------------------------
__global__ __launch_bounds__(256)
void conv_hs_kernel(const float* __restrict__ hs) {
    size_t i = ((size_t)blockIdx.x * 256 + threadIdx.x) * 4;
    if (i >= (size_t)MPAD * EE) return;
    size_t row = i >> 10;
    float4 v = make_float4(0.f, 0.f, 0.f, 0.f);
    if (row < MM) v = *(const float4*)(hs + i);
    __nv_bfloat162* dst = (__nv_bfloat162*)(g_hsb + i);
    dst[0] = __nv_bfloat162(__float2bfloat16(v.x), __float2bfloat16(v.y));
    dst[1] = __nv_bfloat162(__float2bfloat16(v.z), __float2bfloat16(v.w));
}

__global__ __launch_bounds__(256)
void conv_W_kernel(const float* __restrict__ W) {
    __shared__ float t[32][33];
    int n0 = blockIdx.x * 32;
    int k0 = blockIdx.y * 32;
    int tx = threadIdx.x;
    int ty = threadIdx.y;
#pragma unroll
    for (int j = 0; j < 32; j += 8)
        t[ty + j][tx] = W[(size_t)(k0 + ty + j) * VV + n0 + tx];
    __syncthreads();
#pragma unroll
    for (int j = 0; j < 32; j += 8)
        g_Wtb[(size_t)(n0 + ty + j) * EE + k0 + tx] = __float2bfloat16(t[tx][ty + j]);
}

__global__ __launch_bounds__(256)
void pad_W_kernel() {
    int i = blockIdx.x * 256 + threadIdx.x;
    if (i < (NPAD - VV) * EE)
        g_Wtb[(size_t)VV * EE + i] = __float2bfloat16(0.f);
}

// ---------------------------------------------------------------------------
// Gather per-batch label columns of W into compact [128][EE] matrices
// ---------------------------------------------------------------------------
__global__ __launch_bounds__(128)
void gather_cols_kernel(const int* __restrict__ ys, const float* __restrict__ bias) {
    const int b = blockIdx.x >> 7;
    const int s = blockIdx.x & 127;
    const int tid = threadIdx.x;
    int col = -1;
    if (s == 0) col = 0;
    else if (s < GG) {
        int y = ys[b * LL + s - 1];
        col = y < 0 ? 0 : y;
    }
    uint4 v = make_uint4(0, 0, 0, 0);
    if (col >= 0) v = *(const uint4*)(g_Wtb + (size_t)col * EE + tid * 8);
    *(uint4*)(g_Wg + ((size_t)(b * 128 + s)) * EE + tid * 8) = v;
    if (tid == 0) g_bias_g[b * 128 + s] = (col >= 0) ? bias[col] : 0.f;
}

// ---------------------------------------------------------------------------
// Main GEMM (bf16 mma.sync, 4 warps, 128x128, warp tile 64x64) + fused LSE
// partials. CTAs whose whole M-tile lies past ilen are skipped.
// ---------------------------------------------------------------------------
__global__ __launch_bounds__(128, 2)
void gemm_lse_kernel(const float* __restrict__ bias, const int* __restrict__ ilens) {
    const int by = blockIdx.y;
    const int row0 = by * BM;
    // Dead-tile skip: tile fully within one batch and entirely past its ilen
    {
        int b0 = row0 / TT;
        int bend = (row0 + BM - 1) / TT;
        if (b0 == bend && (row0 % TT) >= ilens[b0]) return;
    }

    extern __shared__ char dsm[];
    __shared__ float2 red[2][BM];

    const int tid = threadIdx.x;
    const int warp = tid >> 5, lane = tid & 31;
    const int wm = (warp & 1) * 64, wn = (warp >> 1) * 64;
    const int bx = blockIdx.x;
    const int col0 = bx * BN;
    const uint32_t sbase = smem_u32(dsm);

    const __nv_bfloat16* srcA = g_hsb + ((size_t)row0 + tid) * EE;
    const __nv_bfloat16* srcB = g_Wtb + ((size_t)col0 + tid) * EE;
    uint32_t dsw[4];
#pragma unroll
    for (int c = 0; c < 4; c++) dsw[c] = swz(tid, c);

    float acc[4][8][4];
#pragma unroll
    for (int mi = 0; mi < 4; mi++)
#pragma unroll
        for (int ni = 0; ni < 8; ni++)
#pragma unroll
            for (int r = 0; r < 4; r++) acc[mi][ni][r] = 0.f;

    uint32_t aoff[2][4], boff[2][4];
#pragma unroll
    for (int kk = 0; kk < 2; kk++) {
#pragma unroll
        for (int mi = 0; mi < 4; mi++) {
            int r = wm + mi * 16 + (lane & 15);
            int c = kk * 2 + (lane >> 4);
            aoff[kk][mi] = sbase + swz(r, c);
        }
#pragma unroll
        for (int nj = 0; nj < 4; nj++) {
            int r = wn + nj * 16 + ((lane >> 4) << 3) + (lane & 7);
            int c = kk * 2 + ((lane >> 3) & 1);
            boff[kk][nj] = sbase + 8192 + swz(r, c);
        }
    }

#define LOAD_STAGE(st, kt) do { \
    uint32_t b_ = (uint32_t)(st) * 16384; \
    const __nv_bfloat16* a_ = srcA + (kt) * BK; \
    const __nv_bfloat16* w_ = srcB + (kt) * BK; \
    cp16(sbase + b_ + dsw[0], a_); \
    cp16(sbase + b_ + dsw[1], a_ + 8); \
    cp16(sbase + b_ + dsw[2], a_ + 16); \
    cp16(sbase + b_ + dsw[3], a_ + 24); \
    cp16(sbase + b_ + 8192 + dsw[0], w_); \
    cp16(sbase + b_ + 8192 + dsw[1], w_ + 8); \
    cp16(sbase + b_ + 8192 + dsw[2], w_ + 16); \
    cp16(sbase + b_ + 8192 + dsw[3], w_ + 24); \
    asm volatile("cp.async.commit_group;" ::: "memory"); \
} while (0)

    LOAD_STAGE(0, 0);
    LOAD_STAGE(1, 1);
    LOAD_STAGE(2, 2);

    for (int kt = 0; kt < KITERS; kt++) {
        const int st = kt & 3;
        if (kt < KITERS - 2)
            asm volatile("cp.async.wait_group 2;" ::: "memory");
        else if (kt == KITERS - 2)
            asm volatile("cp.async.wait_group 1;" ::: "memory");
        else
            asm volatile("cp.async.wait_group 0;" ::: "memory");
        __syncthreads();

        const uint32_t stb = (uint32_t)st * 16384;
#pragma unroll
        for (int kk = 0; kk < 2; kk++) {
            uint32_t af[4][4], bf[4][4];
#pragma unroll
            for (int mi = 0; mi < 4; mi++)
                asm volatile("ldmatrix.sync.aligned.m8n8.x4.shared.b16 {%0,%1,%2,%3}, [%4];"
                             : "=r"(af[mi][0]), "=r"(af[mi][1]), "=r"(af[mi][2]), "=r"(af[mi][3])
                             : "r"(aoff[kk][mi] + stb));
#pragma unroll
            for (int nj = 0; nj < 4; nj++)
                asm volatile("ldmatrix.sync.aligned.m8n8.x4.shared.b16 {%0,%1,%2,%3}, [%4];"
                             : "=r"(bf[nj][0]), "=r"(bf[nj][1]), "=r"(bf[nj][2]), "=r"(bf[nj][3])
                             : "r"(boff[kk][nj] + stb));
#pragma unroll
            for (int mi = 0; mi < 4; mi++)
#pragma unroll
                for (int ni = 0; ni < 8; ni++)
                    asm volatile(
                        "mma.sync.aligned.m16n8k16.row.col.f32.bf16.bf16.f32 "
                        "{%0,%1,%2,%3}, {%4,%5,%6,%7}, {%8,%9}, {%0,%1,%2,%3};"
                        : "+f"(acc[mi][ni][0]), "+f"(acc[mi][ni][1]),
                          "+f"(acc[mi][ni][2]), "+f"(acc[mi][ni][3])
                        : "r"(af[mi][0]), "r"(af[mi][1]), "r"(af[mi][2]), "r"(af[mi][3]),
                          "r"(bf[ni >> 1][(ni & 1) * 2]), "r"(bf[ni >> 1][(ni & 1) * 2 + 1]));
        }
        if (kt + 3 < KITERS) LOAD_STAGE((kt + 3) & 3, kt + 3);
    }
#undef LOAD_STAGE

    // Fused LSE epilogue
#pragma unroll
    for (int mi = 0; mi < 4; mi++) {
        float m1 = NEGF, s1 = 0.f, m2 = NEGF, s2 = 0.f;
#pragma unroll
        for (int ni = 0; ni < 8; ni++) {
            int gcol = col0 + wn + ni * 8 + 2 * (lane & 3);
            float b0 = 0.f, b1 = 0.f;
            bool ok = gcol < VV;
            if (ok) { float2 bv = *(const float2*)(bias + gcol); b0 = bv.x; b1 = bv.y; }
            float v;
            v = ok ? acc[mi][ni][0] + b0 : NEGF;
            if (v > m1) { s1 = s1 * __expf(m1 - v) + 1.f; m1 = v; } else s1 += __expf(v - m1);
            v = ok ? acc[mi][ni][1] + b1 : NEGF;
            if (v > m1) { s1 = s1 * __expf(m1 - v) + 1.f; m1 = v; } else s1 += __expf(v - m1);
            v = ok ? acc[mi][ni][2] + b0 : NEGF;
            if (v > m2) { s2 = s2 * __expf(m2 - v) + 1.f; m2 = v; } else s2 += __expf(v - m2);
            v = ok ? acc[mi][ni][3] + b1 : NEGF;
            if (v > m2) { s2 = s2 * __expf(m2 - v) + 1.f; m2 = v; } else s2 += __expf(v - m2);
        }
#pragma unroll
        for (int msk = 1; msk <= 2; msk <<= 1) {
            float om = __shfl_xor_sync(0xffffffffu, m1, msk);
            float os = __shfl_xor_sync(0xffffffffu, s1, msk);
            float M = fmaxf(m1, om);
            s1 = s1 * __expf(m1 - M) + os * __expf(om - M);
            m1 = M;
            om = __shfl_xor_sync(0xffffffffu, m2, msk);
            os = __shfl_xor_sync(0xffffffffu, s2, msk);
            M = fmaxf(m2, om);
            s2 = s2 * __expf(m2 - M) + os * __expf(om - M);
            m2 = M;
        }
        if ((lane & 3) == 0) {
            int r1 = wm + mi * 16 + (lane >> 2);
            red[warp >> 1][r1] = make_float2(m1, s1);
            red[warp >> 1][r1 + 8] = make_float2(m2, s2);
        }
    }
    __syncthreads();
    {
        float2 p0 = red[0][tid];
        float2 p1 = red[1][tid];
        float M = fmaxf(p0.x, p1.x);
        float s = p0.y * __expf(p0.x - M) + p1.y * __expf(p1.x - M);
        int grow = row0 + tid;
        if (grow < MM) g_part[(size_t)grow * NTILES + bx] = make_float2(M, s);
    }
}

// ---------------------------------------------------------------------------
// lp GEMM: per batch, K split 4. Skips M-tiles past ilen.
// ---------------------------------------------------------------------------
__global__ __launch_bounds__(128, 2)
void lp_gemm_kernel(const int* __restrict__ ilens) {
    const int mt = blockIdx.x;         // 0..3
    const int b  = blockIdx.z;         // 0..15
    if (mt * 128 >= ilens[b]) return;

    extern __shared__ char dsm[];
    const int tid = threadIdx.x;
    const int warp = tid >> 5, lane = tid & 31;
    const int wm = (warp & 1) * 64, wn = (warp >> 1) * 64;
    const int ks = blockIdx.y;         // 0..3
    const int row0 = b * TT + mt * 128;
    const int kb = ks * LPK;
    const uint32_t sbase = smem_u32(dsm);

    const __nv_bfloat16* srcA = g_hsb + ((size_t)row0 + tid) * EE + kb;
    const __nv_bfloat16* srcB = g_Wg + ((size_t)(b * 128) + tid) * EE + kb;
    uint32_t dsw[4];
#pragma unroll
    for (int c = 0; c < 4; c++) dsw[c] = swz(tid, c);

    float acc[4][8][4];
#pragma unroll
    for (int mi = 0; mi < 4; mi++)
#pragma unroll
        for (int ni = 0; ni < 8; ni++)
#pragma unroll
            for (int r = 0; r < 4; r++) acc[mi][ni][r] = 0.f;

    uint32_t aoff[2][4], boff[2][4];
#pragma unroll
    for (int kk = 0; kk < 2; kk++) {
#pragma unroll
        for (int mi = 0; mi < 4; mi++) {
            int r = wm + mi * 16 + (lane & 15);
            int c = kk * 2 + (lane >> 4);
            aoff[kk][mi] = sbase + swz(r, c);
        }
#pragma unroll
        for (int nj = 0; nj < 4; nj++) {
            int r = wn + nj * 16 + ((lane >> 4) << 3) + (lane & 7);
            int c = kk * 2 + ((lane >> 3) & 1);
            boff[kk][nj] = sbase + 8192 + swz(r, c);
        }
    }

#define LOAD_STAGE(st, kt) do { \
    uint32_t b_ = (uint32_t)(st) * 16384; \
    const __nv_bfloat16* a_ = srcA + (kt) * BK; \
    const __nv_bfloat16* w_ = srcB + (kt) * BK; \
    cp16(sbase + b_ + dsw[0], a_); \
    cp16(sbase + b_ + dsw[1], a_ + 8); \
    cp16(sbase + b_ + dsw[2], a_ + 16); \
    cp16(sbase + b_ + dsw[3], a_ + 24); \
    cp16(sbase + b_ + 8192 + dsw[0], w_); \
    cp16(sbase + b_ + 8192 + dsw[1], w_ + 8); \
    cp16(sbase + b_ + 8192 + dsw[2], w_ + 16); \
    cp16(sbase + b_ + 8192 + dsw[3], w_ + 24); \
    asm volatile("cp.async.commit_group;" ::: "memory"); \
} while (0)

    LOAD_STAGE(0, 0);
    LOAD_STAGE(1, 1);
    LOAD_STAGE(2, 2);

    for (int kt = 0; kt < LPKIT; kt++) {
        const int st = kt & 3;
        if (kt < LPKIT - 2)
            asm volatile("cp.async.wait_group 2;" ::: "memory");
        else if (kt == LPKIT - 2)
            asm volatile("cp.async.wait_group 1;" ::: "memory");
        else
            asm volatile("cp.async.wait_group 0;" ::: "memory");
        __syncthreads();

        const uint32_t stb = (uint32_t)st * 16384;
#pragma unroll
        for (int kk = 0; kk < 2; kk++) {
            uint32_t af[4][4], bf[4][4];
#pragma unroll
            for (int mi = 0; mi < 4; mi++)
                asm volatile("ldmatrix.sync.aligned.m8n8.x4.shared.b16 {%0,%1,%2,%3}, [%4];"
                             : "=r"(af[mi][0]), "=r"(af[mi][1]), "=r"(af[mi][2]), "=r"(af[mi][3])
                             : "r"(aoff[kk][mi] + stb));
#pragma unroll
            for (int nj = 0; nj < 4; nj++)
                asm volatile("ldmatrix.sync.aligned.m8n8.x4.shared.b16 {%0,%1,%2,%3}, [%4];"
                             : "=r"(bf[nj][0]), "=r"(bf[nj][1]), "=r"(bf[nj][2]), "=r"(bf[nj][3])
                             : "r"(boff[kk][nj] + stb));
#pragma unroll
            for (int mi = 0; mi < 4; mi++)
#pragma unroll
                for (int ni = 0; ni < 8; ni++)
                    asm volatile(
                        "mma.sync.aligned.m16n8k16.row.col.f32.bf16.bf16.f32 "
                        "{%0,%1,%2,%3}, {%4,%5,%6,%7}, {%8,%9}, {%0,%1,%2,%3};"
                        : "+f"(acc[mi][ni][0]), "+f"(acc[mi][ni][1]),
                          "+f"(acc[mi][ni][2]), "+f"(acc[mi][ni][3])
                        : "r"(af[mi][0]), "r"(af[mi][1]), "r"(af[mi][2]), "r"(af[mi][3]),
                          "r"(bf[ni >> 1][(ni & 1) * 2]), "r"(bf[ni >> 1][(ni & 1) * 2 + 1]));
        }
        if (kt + 3 < LPKIT) LOAD_STAGE((kt + 3) & 3, kt + 3);
    }
#undef LOAD_STAGE

#pragma unroll
    for (int mi = 0; mi < 4; mi++) {
        int lr1 = mt * 128 + wm + mi * 16 + (lane >> 2);
        int s = wn + 2 * (lane & 3);
#pragma unroll
        for (int ni = 0; ni < 8; ni++) {
            int sc = s + ni * 8;
            if (lr1 < TT) {
                int gr = b * TT + lr1;
                *(float2*)(g_lpp + ((size_t)ks * MM + gr) * 128 + sc) =
                    make_float2(acc[mi][ni][0], acc[mi][ni][1]);
            }
            if (lr1 + 8 < TT) {
                int gr = b * TT + lr1 + 8;
                *(float2*)(g_lpp + ((size_t)ks * MM + gr) * 128 + sc) =
                    make_float2(acc[mi][ni][2], acc[mi][ni][3]);
            }
        }
    }
}

// ---------------------------------------------------------------------------
// Combine: lse reduce (warp 0) + lp = sum_k partials + bias - lse
// ---------------------------------------------------------------------------
__global__ __launch_bounds__(128)
void combine_kernel(const int* __restrict__ ilens) {
    const int row = blockIdx.x;
    const int b = row / TT;
    if ((row % TT) >= ilens[b]) return;

    __shared__ float s_lse;
    const int tid = threadIdx.x;
    if (tid < 32) {
        float2 p = g_part[(size_t)row * NTILES + tid];
        float m = p.x, s = p.y;
#pragma unroll
        for (int msk = 16; msk > 0; msk >>= 1) {
            float om = __shfl_xor_sync(0xffffffffu, m, msk);
            float os = __shfl_xor_sync(0xffffffffu, s, msk);
            float M = fmaxf(m, om);
            s = s * __expf(m - M) + os * __expf(om - M);
            m = M;
        }
        if (tid == 0) s_lse = m + logf(s);
    }
    __syncthreads();
    if (tid >= GG) return;
    float acc = 0.f;
#pragma unroll
    for (int ks = 0; ks < KSPLIT; ks++)
        acc += g_lpp[((size_t)ks * MM + row) * 128 + tid];
    g_lp[(size_t)row * GG + tid] = acc + g_bias_g[b * 128 + tid] - s_lse;
}

// ---------------------------------------------------------------------------
// CTC forward DP, one block per batch element; stages only ilen rows.
// ---------------------------------------------------------------------------
__global__ __launch_bounds__(256)
void ctc_dp_kernel(const int* __restrict__ ys, const int* __restrict__ ilens,
                   const int* __restrict__ olens) {
    extern __shared__ float sm[];
    float* lps = sm;                     // [<=TT][GG]
    float* abuf = sm + TT * GG;          // [2][256]

    const int b = blockIdx.x;
    const int tid = threadIdx.x;
    const int s = tid;
    const int ilen = ilens[b];

    const float* src = g_lp + (size_t)b * TT * GG;
    for (int i = tid; i < ilen * GG; i += blockDim.x) lps[i] = src[i];

    int g = 0;
    bool allow = false;
    if (s < SS && (s & 1)) {
        int l = s >> 1;
        g = 1 + l;
        int yr = ys[b * LL + l];
        int y = yr < 0 ? 0 : yr;
        int ypr = -1;
        if (l > 0) {
            int yp = ys[b * LL + l - 1];
            ypr = yp < 0 ? 0 : yp;
        }
        allow = (y != 0) && (y != ypr);
    }

    float* a0 = abuf;
    float* a1 = abuf + 256;
    a0[s] = (s == 0) ? lps[0] : ((s == 1) ? lps[1] : NEGF);
    __syncthreads();

    for (int t = 1; t < ilen; t++) {
        if (s < SS) {
            float v1 = a0[s];
            float v2 = (s >= 1) ? a0[s - 1] : NEGF;
            float v3 = (s >= 2 && allow) ? a0[s - 2] : NEGF;
            float m = fmaxf(v1, fmaxf(v2, v3));
            float sum = __expf(v1 - m) + __expf(v2 - m) + __expf(v3 - m);
            a1[s] = m + __logf(sum) + lps[t * GG + g];
        }
        __syncthreads();
        float* tmp = a0; a0 = a1; a1 = tmp;
    }

    if (tid == 0) {
        const int olen = olens[b];
        float va = a0[2 * olen];
        float vb = a0[2 * olen - 1];
        float m = fmaxf(va, vb);
        g_ll[b] = m + logf(expf(va - m) + expf(vb - m));
    }
}

__global__ void finalize_kernel(float* __restrict__ out) {
    if (threadIdx.x == 0) {
        float sum = 0.0f;
        for (int i = 0; i < BSZ; i++) sum += g_ll[i];
        out[0] = -sum / (float)BSZ;
    }
}

// ---------------------------------------------------------------------------
extern "C" void kernel_launch(void* const* d_in, const int* in_sizes, int n_in,
                              void* d_out, int out_size) {
    const float* hs    = (const float*)d_in[0];
    const float* W     = (const float*)d_in[1];
    const float* bias  = (const float*)d_in[2];
    const int*   ys    = (const int*)d_in[3];
    const int*   ilens = (const int*)d_in[4];
    const int*   olens = (const int*)d_in[5];
    float* out = (float*)d_out;

    conv_hs_kernel<<<(MPAD * EE) / 1024, 256>>>(hs);
    conv_W_kernel<<<dim3(VV / 32, EE / 32), dim3(32, 8)>>>(W);
    pad_W_kernel<<<((NPAD - VV) * EE + 255) / 256, 256>>>();
    gather_cols_kernel<<<BSZ * 128, 128>>>(ys, bias);

    const int gemm_smem = NST * 16384;   // 64 KB
    cudaFuncSetAttribute(gemm_lse_kernel,
                         cudaFuncAttributeMaxDynamicSharedMemorySize, gemm_smem);
    dim3 ggrid(NPAD / BN, MPAD / BM);    // 32 x 63
    gemm_lse_kernel<<<ggrid, 128, gemm_smem>>>(bias, ilens);

    cudaFuncSetAttribute(lp_gemm_kernel,
                         cudaFuncAttributeMaxDynamicSharedMemorySize, gemm_smem);
    lp_gemm_kernel<<<dim3(4, KSPLIT, BSZ), 128, gemm_smem>>>(ilens);

    combine_kernel<<<MM, 128>>>(ilens);

    const int dp_smem = TT * GG * sizeof(float) + 2 * 256 * sizeof(float);
    cudaFuncSetAttribute(ctc_dp_kernel,
                         cudaFuncAttributeMaxDynamicSharedMemorySize, dp_smem);
    ctc_dp_kernel<<<BSZ, 256, dp_smem>>>(ys, ilens, olens);

    finalize_kernel<<<1, 32>>>(out);
}

// round 7
// speedup vs baseline: 1.7917x; 1.0470x over previous
#include <cuda_runtime.h>
#include <cuda_bf16.h>
#include <math.h>
#include <stdint.h>

// Problem constants
#define BSZ 16
#define TT  500
#define EE  1024
#define VV  4000
#define LL  100
#define SS  201
#define GG  101
#define MM  (BSZ*TT)     // 8000
#define MPAD 8064        // 63*128
#define NPAD 4096        // 32*128
#define NEGF (-1e30f)
#define SELP 112         // padded stride for g_sel rows

// GEMM tiling (4 warps, warp tile 64x64) -- proven R4 config
#define BM 128
#define BN 128
#define BK 32
#define NST 4
#define KITERS (EE/BK)   // 32
#define NTILES (NPAD/BN) // 32

// Scratch (device globals: allocation-free per harness rules)
__device__ __nv_bfloat16 g_hsb[(size_t)MPAD * EE];
__device__ __nv_bfloat16 g_Wtb[(size_t)NPAD * EE];
__device__ int g_colidx[(size_t)BSZ * VV];   // col -> unique state idx (-1 unused)
__device__ int g_us[BSZ * GG];               // state s -> unique idx
__device__ float2 g_part[(size_t)MM * NTILES];
__device__ float g_sel[(size_t)MM * SELP];   // selected logits (bias added)
__device__ float g_lp[(size_t)MM * GG];
__device__ float g_ll[BSZ];

// ---------------------------------------------------------------------------
__device__ __forceinline__ uint32_t smem_u32(const void* p) {
    uint32_t a;
    asm("{ .reg .u64 t; cvta.to.shared.u64 t, %1; cvt.u32.u64 %0, t; }" : "=r"(a) : "l"(p));
    return a;
}
__device__ __forceinline__ void cp16(uint32_t dst, const void* src) {
    asm volatile("cp.async.cg.shared.global [%0], [%1], 16;" :: "r"(dst), "l"(src));
}
__device__ __forceinline__ uint32_t swz(int row, int c) {
    return (uint32_t)(row * 64 + ((c ^ ((row >> 1) & 3)) << 4));
}

// ---------------------------------------------------------------------------
// Conversion kernels
// ---------------------------------------------------------------------------
__global__ __launch_bounds__(256)
void conv_hs_kernel(const float* __restrict__ hs) {
    size_t i = ((size_t)blockIdx.x * 256 + threadIdx.x) * 4;
    if (i >= (size_t)MPAD * EE) return;
    size_t row = i >> 10;
    float4 v = make_float4(0.f, 0.f, 0.f, 0.f);
    if (row < MM) v = *(const float4*)(hs + i);
    __nv_bfloat162* dst = (__nv_bfloat162*)(g_hsb + i);
    dst[0] = __nv_bfloat162(__float2bfloat16(v.x), __float2bfloat16(v.y));
    dst[1] = __nv_bfloat162(__float2bfloat16(v.z), __float2bfloat16(v.w));
}

__global__ __launch_bounds__(256)
void conv_W_kernel(const float* __restrict__ W) {
    __shared__ float t[32][33];
    int n0 = blockIdx.x * 32;
    int k0 = blockIdx.y * 32;
    int tx = threadIdx.x;
    int ty = threadIdx.y;
#pragma unroll
    for (int j = 0; j < 32; j += 8)
        t[ty + j][tx] = W[(size_t)(k0 + ty + j) * VV + n0 + tx];
    __syncthreads();
#pragma unroll
    for (int j = 0; j < 32; j += 8)
        g_Wtb[(size_t)(n0 + ty + j) * EE + k0 + tx] = __float2bfloat16(t[tx][ty + j]);
}

__global__ __launch_bounds__(256)
void pad_W_kernel() {
    int i = blockIdx.x * 256 + threadIdx.x;
    if (i < (NPAD - VV) * EE)
        g_Wtb[(size_t)VV * EE + i] = __float2bfloat16(0.f);
}

// ---------------------------------------------------------------------------
// Build per-batch column maps: g_colidx[b][col] = unique idx, g_us[b][s] = idx
// ---------------------------------------------------------------------------
__global__ __launch_bounds__(256)
void build_map_kernel(const int* __restrict__ ys) {
    const int b = blockIdx.x;
    for (int i = threadIdx.x; i < VV; i += blockDim.x)
        g_colidx[(size_t)b * VV + i] = -1;
    __syncthreads();
    if (threadIdx.x == 0) {
        for (int s = 0; s < GG; s++) {
            int col = 0;
            if (s > 0) {
                int y = ys[b * LL + s - 1];
                col = y < 0 ? 0 : y;
            }
            int u = g_colidx[(size_t)b * VV + col];
            if (u < 0) { u = s; g_colidx[(size_t)b * VV + col] = s; }
            g_us[b * GG + s] = u;
        }
    }
}

// ---------------------------------------------------------------------------
// Main GEMM (bf16 mma.sync, 4 warps, 128x128, warp tile 64x64) with fused
// LSE partials + selected-logit scatter. Dead M-tiles (past ilen) skipped.
// ---------------------------------------------------------------------------
__global__ __launch_bounds__(128, 2)
void gemm_lse_kernel(const float* __restrict__ bias, const int* __restrict__ ilens) {
    const int by = blockIdx.y;
    const int row0 = by * BM;
    {
        int b0 = row0 / TT;
        int bend = (row0 + BM - 1) / TT;
        if (b0 == bend && (row0 % TT) >= ilens[b0]) return;
    }

    extern __shared__ char dsm[];
    __shared__ float2 red[2][BM];

    const int tid = threadIdx.x;
    const int warp = tid >> 5, lane = tid & 31;
    const int wm = (warp & 1) * 64, wn = (warp >> 1) * 64;
    const int bx = blockIdx.x;
    const int col0 = bx * BN;
    const uint32_t sbase = smem_u32(dsm);

    const __nv_bfloat16* srcA = g_hsb + ((size_t)row0 + tid) * EE;
    const __nv_bfloat16* srcB = g_Wtb + ((size_t)col0 + tid) * EE;
    uint32_t dsw[4];
#pragma unroll
    for (int c = 0; c < 4; c++) dsw[c] = swz(tid, c);

    float acc[4][8][4];
#pragma unroll
    for (int mi = 0; mi < 4; mi++)
#pragma unroll
        for (int ni = 0; ni < 8; ni++)
#pragma unroll
            for (int r = 0; r < 4; r++) acc[mi][ni][r] = 0.f;

    uint32_t aoff[2][4], boff[2][4];
#pragma unroll
    for (int kk = 0; kk < 2; kk++) {
#pragma unroll
        for (int mi = 0; mi < 4; mi++) {
            int r = wm + mi * 16 + (lane & 15);
            int c = kk * 2 + (lane >> 4);
            aoff[kk][mi] = sbase + swz(r, c);
        }
#pragma unroll
        for (int nj = 0; nj < 4; nj++) {
            int r = wn + nj * 16 + ((lane >> 4) << 3) + (lane & 7);
            int c = kk * 2 + ((lane >> 3) & 1);
            boff[kk][nj] = sbase + 8192 + swz(r, c);
        }
    }

#define LOAD_STAGE(st, kt) do { \
    uint32_t b_ = (uint32_t)(st) * 16384; \
    const __nv_bfloat16* a_ = srcA + (kt) * BK; \
    const __nv_bfloat16* w_ = srcB + (kt) * BK; \
    cp16(sbase + b_ + dsw[0], a_); \
    cp16(sbase + b_ + dsw[1], a_ + 8); \
    cp16(sbase + b_ + dsw[2], a_ + 16); \
    cp16(sbase + b_ + dsw[3], a_ + 24); \
    cp16(sbase + b_ + 8192 + dsw[0], w_); \
    cp16(sbase + b_ + 8192 + dsw[1], w_ + 8); \
    cp16(sbase + b_ + 8192 + dsw[2], w_ + 16); \
    cp16(sbase + b_ + 8192 + dsw[3], w_ + 24); \
    asm volatile("cp.async.commit_group;" ::: "memory"); \
} while (0)

    LOAD_STAGE(0, 0);
    LOAD_STAGE(1, 1);
    LOAD_STAGE(2, 2);

    for (int kt = 0; kt < KITERS; kt++) {
        const int st = kt & 3;
        if (kt < KITERS - 2)
            asm volatile("cp.async.wait_group 2;" ::: "memory");
        else if (kt == KITERS - 2)
            asm volatile("cp.async.wait_group 1;" ::: "memory");
        else
            asm volatile("cp.async.wait_group 0;" ::: "memory");
        __syncthreads();

        const uint32_t stb = (uint32_t)st * 16384;
#pragma unroll
        for (int kk = 0; kk < 2; kk++) {
            uint32_t af[4][4], bf[4][4];
#pragma unroll
            for (int mi = 0; mi < 4; mi++)
                asm volatile("ldmatrix.sync.aligned.m8n8.x4.shared.b16 {%0,%1,%2,%3}, [%4];"
                             : "=r"(af[mi][0]), "=r"(af[mi][1]), "=r"(af[mi][2]), "=r"(af[mi][3])
                             : "r"(aoff[kk][mi] + stb));
#pragma unroll
            for (int nj = 0; nj < 4; nj++)
                asm volatile("ldmatrix.sync.aligned.m8n8.x4.shared.b16 {%0,%1,%2,%3}, [%4];"
                             : "=r"(bf[nj][0]), "=r"(bf[nj][1]), "=r"(bf[nj][2]), "=r"(bf[nj][3])
                             : "r"(boff[kk][nj] + stb));
#pragma unroll
            for (int mi = 0; mi < 4; mi++)
#pragma unroll
                for (int ni = 0; ni < 8; ni++)
                    asm volatile(
                        "mma.sync.aligned.m16n8k16.row.col.f32.bf16.bf16.f32 "
                        "{%0,%1,%2,%3}, {%4,%5,%6,%7}, {%8,%9}, {%0,%1,%2,%3};"
                        : "+f"(acc[mi][ni][0]), "+f"(acc[mi][ni][1]),
                          "+f"(acc[mi][ni][2]), "+f"(acc[mi][ni][3])
                        : "r"(af[mi][0]), "r"(af[mi][1]), "r"(af[mi][2]), "r"(af[mi][3]),
                          "r"(bf[ni >> 1][(ni & 1) * 2]), "r"(bf[ni >> 1][(ni & 1) * 2 + 1]));
        }
        if (kt + 3 < KITERS) LOAD_STAGE((kt + 3) & 3, kt + 3);
    }
#undef LOAD_STAGE

    // Epilogue: bias add, selected-logit scatter, LSE partials (max then sum)
#pragma unroll
    for (int mi = 0; mi < 4; mi++) {
        const int r1 = row0 + wm + mi * 16 + (lane >> 2);
        const int r2 = r1 + 8;
        const int b1 = r1 / TT;
        const int b2 = r2 / TT;
        float vv1[16], vv2[16];
#pragma unroll
        for (int ni = 0; ni < 8; ni++) {
            int gcol = col0 + wn + ni * 8 + 2 * (lane & 3);
            bool ok = gcol < VV;
            float b0 = 0.f, bb = 0.f;
            if (ok) { float2 bv = *(const float2*)(bias + gcol); b0 = bv.x; bb = bv.y; }
            float a0 = acc[mi][ni][0] + b0, a1 = acc[mi][ni][1] + bb;
            float a2 = acc[mi][ni][2] + b0, a3 = acc[mi][ni][3] + bb;
            vv1[2 * ni] = ok ? a0 : NEGF; vv1[2 * ni + 1] = ok ? a1 : NEGF;
            vv2[2 * ni] = ok ? a2 : NEGF; vv2[2 * ni + 1] = ok ? a3 : NEGF;
            if (ok && r1 < MM) {
                int u0 = g_colidx[(size_t)b1 * VV + gcol];
                int u1 = g_colidx[(size_t)b1 * VV + gcol + 1];
                if (u0 >= 0) g_sel[(size_t)r1 * SELP + u0] = a0;
                if (u1 >= 0) g_sel[(size_t)r1 * SELP + u1] = a1;
            }
            if (ok && r2 < MM) {
                int u0 = g_colidx[(size_t)b2 * VV + gcol];
                int u1 = g_colidx[(size_t)b2 * VV + gcol + 1];
                if (u0 >= 0) g_sel[(size_t)r2 * SELP + u0] = a2;
                if (u1 >= 0) g_sel[(size_t)r2 * SELP + u1] = a3;
            }
        }
        // max-then-sum (breaks serial exp dependency)
        float m1 = vv1[0], m2 = vv2[0];
#pragma unroll
        for (int j = 1; j < 16; j++) { m1 = fmaxf(m1, vv1[j]); m2 = fmaxf(m2, vv2[j]); }
        float s1 = 0.f, s2 = 0.f;
#pragma unroll
        for (int j = 0; j < 16; j++) { s1 += __expf(vv1[j] - m1); s2 += __expf(vv2[j] - m2); }

#pragma unroll
        for (int msk = 1; msk <= 2; msk <<= 1) {
            float om = __shfl_xor_sync(0xffffffffu, m1, msk);
            float os = __shfl_xor_sync(0xffffffffu, s1, msk);
            float M = fmaxf(m1, om);
            s1 = s1 * __expf(m1 - M) + os * __expf(om - M);
            m1 = M;
            om = __shfl_xor_sync(0xffffffffu, m2, msk);
            os = __shfl_xor_sync(0xffffffffu, s2, msk);
            M = fmaxf(m2, om);
            s2 = s2 * __expf(m2 - M) + os * __expf(om - M);
            m2 = M;
        }
        if ((lane & 3) == 0) {
            int rr = wm + mi * 16 + (lane >> 2);
            red[warp >> 1][rr] = make_float2(m1, s1);
            red[warp >> 1][rr + 8] = make_float2(m2, s2);
        }
    }
    __syncthreads();
    {
        float2 p0 = red[0][tid];
        float2 p1 = red[1][tid];
        float M = fmaxf(p0.x, p1.x);
        float s = p0.y * __expf(p0.x - M) + p1.y * __expf(p1.x - M);
        int grow = row0 + tid;
        if (grow < MM) g_part[(size_t)grow * NTILES + bx] = make_float2(M, s);
    }
}

// ---------------------------------------------------------------------------
// Combine: lse reduce (warp 0) + lp[row][s] = sel[row][us[s]] - lse
// ---------------------------------------------------------------------------
__global__ __launch_bounds__(128)
void combine_kernel(const int* __restrict__ ilens) {
    const int row = blockIdx.x;
    const int b = row / TT;
    if ((row % TT) >= ilens[b]) return;

    __shared__ float s_lse;
    const int tid = threadIdx.x;
    if (tid < 32) {
        float2 p = g_part[(size_t)row * NTILES + tid];
        float m = p.x, s = p.y;
#pragma unroll
        for (int msk = 16; msk > 0; msk >>= 1) {
            float om = __shfl_xor_sync(0xffffffffu, m, msk);
            float os = __shfl_xor_sync(0xffffffffu, s, msk);
            float M = fmaxf(m, om);
            s = s * __expf(m - M) + os * __expf(om - M);
            m = M;
        }
        if (tid == 0) s_lse = m + logf(s);
    }
    __syncthreads();
    if (tid >= GG) return;
    int u = g_us[b * GG + tid];
    g_lp[(size_t)row * GG + tid] = g_sel[(size_t)row * SELP + u] - s_lse;
}

// ---------------------------------------------------------------------------
// CTC forward DP, one block per batch element; stages only ilen rows.
// ---------------------------------------------------------------------------
__global__ __launch_bounds__(256)
void ctc_dp_kernel(const int* __restrict__ ys, const int* __restrict__ ilens,
                   const int* __restrict__ olens) {
    extern __shared__ float sm[];
    float* lps = sm;                     // [<=TT][GG]
    float* abuf = sm + TT * GG;          // [2][256]

    const int b = blockIdx.x;
    const int tid = threadIdx.x;
    const int s = tid;
    const int ilen = ilens[b];

    const float* src = g_lp + (size_t)b * TT * GG;
    for (int i = tid; i < ilen * GG; i += blockDim.x) lps[i] = src[i];

    int g = 0;
    bool allow = false;
    if (s < SS && (s & 1)) {
        int l = s >> 1;
        g = 1 + l;
        int yr = ys[b * LL + l];
        int y = yr < 0 ? 0 : yr;
        int ypr = -1;
        if (l > 0) {
            int yp = ys[b * LL + l - 1];
            ypr = yp < 0 ? 0 : yp;
        }
        allow = (y != 0) && (y != ypr);
    }

    float* a0 = abuf;
    float* a1 = abuf + 256;
    a0[s] = (s == 0) ? lps[0] : ((s == 1) ? lps[1] : NEGF);
    __syncthreads();

    for (int t = 1; t < ilen; t++) {
        if (s < SS) {
            float v1 = a0[s];
            float v2 = (s >= 1) ? a0[s - 1] : NEGF;
            float v3 = (s >= 2 && allow) ? a0[s - 2] : NEGF;
            float m = fmaxf(v1, fmaxf(v2, v3));
            float sum = __expf(v1 - m) + __expf(v2 - m) + __expf(v3 - m);
            a1[s] = m + __logf(sum) + lps[t * GG + g];
        }
        __syncthreads();
        float* tmp = a0; a0 = a1; a1 = tmp;
    }

    if (tid == 0) {
        const int olen = olens[b];
        float va = a0[2 * olen];
        float vb = a0[2 * olen - 1];
        float m = fmaxf(va, vb);
        g_ll[b] = m + logf(expf(va - m) + expf(vb - m));
    }
}

__global__ void finalize_kernel(float* __restrict__ out) {
    if (threadIdx.x == 0) {
        float sum = 0.0f;
        for (int i = 0; i < BSZ; i++) sum += g_ll[i];
        out[0] = -sum / (float)BSZ;
    }
}

// ---------------------------------------------------------------------------
extern "C" void kernel_launch(void* const* d_in, const int* in_sizes, int n_in,
                              void* d_out, int out_size) {
    const float* hs    = (const float*)d_in[0];
    const float* W     = (const float*)d_in[1];
    const float* bias  = (const float*)d_in[2];
    const int*   ys    = (const int*)d_in[3];
    const int*   ilens = (const int*)d_in[4];
    const int*   olens = (const int*)d_in[5];
    float* out = (float*)d_out;

    conv_hs_kernel<<<(MPAD * EE) / 1024, 256>>>(hs);
    conv_W_kernel<<<dim3(VV / 32, EE / 32), dim3(32, 8)>>>(W);
    pad_W_kernel<<<((NPAD - VV) * EE + 255) / 256, 256>>>();
    build_map_kernel<<<BSZ, 256>>>(ys);

    const int gemm_smem = NST * 16384;   // 64 KB
    cudaFuncSetAttribute(gemm_lse_kernel,
                         cudaFuncAttributeMaxDynamicSharedMemorySize, gemm_smem);
    dim3 ggrid(NPAD / BN, MPAD / BM);    // 32 x 63
    gemm_lse_kernel<<<ggrid, 128, gemm_smem>>>(bias, ilens);

    combine_kernel<<<MM, 128>>>(ilens);

    const int dp_smem = TT * GG * sizeof(float) + 2 * 256 * sizeof(float);
    cudaFuncSetAttribute(ctc_dp_kernel,
                         cudaFuncAttributeMaxDynamicSharedMemorySize, dp_smem);
    ctc_dp_kernel<<<BSZ, 256, dp_smem>>>(ys, ilens, olens);

    finalize_kernel<<<1, 32>>>(out);
}

// round 8
// speedup vs baseline: 1.9867x; 1.1088x over previous
#include <cuda_runtime.h>
#include <cuda_bf16.h>
#include <math.h>
#include <stdint.h>

// Problem constants
#define BSZ 16
#define TT  500
#define EE  1024
#define VV  4000
#define LL  100
#define SS  201
#define GG  101
#define MM  (BSZ*TT)     // 8000
#define MPAD 8064        // 63*128
#define NPAD 4096        // 32*128
#define NEGF (-1e30f)
#define SELP 112
#define UNUSED_SENT 0x7fffffff

// GEMM tiling (4 warps, warp tile 64x64)
#define BM 128
#define BN 128
#define BK 32
#define NST 4
#define KITERS (EE/BK)   // 32
#define NTILES (NPAD/BN) // 32

// Scratch (device globals: allocation-free per harness rules)
__device__ __nv_bfloat16 g_hsb[(size_t)MPAD * EE];   // COMPACT rows; dead rows zero
__device__ __nv_bfloat16 g_Wtb[(size_t)NPAD * EE];
__device__ int g_colidx[(size_t)BSZ * VV];           // col -> unique state idx (INT_MAX unused)
__device__ int g_us[BSZ * GG];
__device__ int g_base[BSZ + 1];                      // compact row offsets per batch
__device__ int g_live;                               // total live rows
__device__ int g_rowsrc[MPAD];                       // compact row -> original row (-1 dead)
__device__ int g_rowb[MPAD];                         // compact row -> batch (-1 dead)
__device__ float2 g_part[(size_t)MM * NTILES];
__device__ float g_sel[(size_t)MM * SELP];
__device__ float g_lp[(size_t)MM * GG];              // compact-row indexed
__device__ float g_ll[BSZ];

// ---------------------------------------------------------------------------
__device__ __forceinline__ uint32_t smem_u32(const void* p) {
    uint32_t a;
    asm("{ .reg .u64 t; cvta.to.shared.u64 t, %1; cvt.u32.u64 %0, t; }" : "=r"(a) : "l"(p));
    return a;
}
__device__ __forceinline__ void cp16(uint32_t dst, const void* src) {
    asm volatile("cp.async.cg.shared.global [%0], [%1], 16;" :: "r"(dst), "l"(src));
}
__device__ __forceinline__ uint32_t swz(int row, int c) {
    return (uint32_t)(row * 64 + ((c ^ ((row >> 1) & 3)) << 4));
}

// ---------------------------------------------------------------------------
// Row compaction setup
// ---------------------------------------------------------------------------
__global__ void prefix_kernel(const int* __restrict__ ilens) {
    if (threadIdx.x == 0) {
        int acc = 0;
        for (int b = 0; b < BSZ; b++) { g_base[b] = acc; acc += ilens[b]; }
        g_base[BSZ] = acc;
        g_live = acc;
    }
}

__global__ __launch_bounds__(256)
void rowmap_init_kernel() {
    int i = blockIdx.x * 256 + threadIdx.x;
    if (i < MPAD) { g_rowsrc[i] = -1; g_rowb[i] = -1; }
}

__global__ __launch_bounds__(256)
void rowmap_build_kernel(const int* __restrict__ ilens) {
    int row = blockIdx.x * 256 + threadIdx.x;
    if (row >= MM) return;
    int b = row / TT, t = row % TT;
    if (t < ilens[b]) {
        int o = g_base[b] + t;
        g_rowsrc[o] = row;
        g_rowb[o] = b;
    }
}

// ---------------------------------------------------------------------------
// Conversion kernels
// ---------------------------------------------------------------------------
__global__ __launch_bounds__(256)
void conv_hs_kernel(const float* __restrict__ hs) {
    size_t i = ((size_t)blockIdx.x * 256 + threadIdx.x) * 4;
    if (i >= (size_t)MPAD * EE) return;
    int orow = (int)(i >> 10);
    int k = (int)(i & 1023);
    int src = g_rowsrc[orow];
    float4 v = make_float4(0.f, 0.f, 0.f, 0.f);
    if (src >= 0) v = *(const float4*)(hs + (size_t)src * EE + k);
    __nv_bfloat162* dst = (__nv_bfloat162*)(g_hsb + i);
    dst[0] = __nv_bfloat162(__float2bfloat16(v.x), __float2bfloat16(v.y));
    dst[1] = __nv_bfloat162(__float2bfloat16(v.z), __float2bfloat16(v.w));
}

__global__ __launch_bounds__(256)
void conv_W_kernel(const float* __restrict__ W) {
    __shared__ float t[32][33];
    int n0 = blockIdx.x * 32;
    int k0 = blockIdx.y * 32;
    int tx = threadIdx.x;
    int ty = threadIdx.y;
#pragma unroll
    for (int j = 0; j < 32; j += 8)
        t[ty + j][tx] = W[(size_t)(k0 + ty + j) * VV + n0 + tx];
    __syncthreads();
#pragma unroll
    for (int j = 0; j < 32; j += 8)
        g_Wtb[(size_t)(n0 + ty + j) * EE + k0 + tx] = __float2bfloat16(t[tx][ty + j]);
}

__global__ __launch_bounds__(256)
void pad_W_kernel() {
    int i = blockIdx.x * 256 + threadIdx.x;
    if (i < (NPAD - VV) * EE)
        g_Wtb[(size_t)VV * EE + i] = __float2bfloat16(0.f);
}

// ---------------------------------------------------------------------------
// Build per-batch column maps (parallel, atomicMin)
// ---------------------------------------------------------------------------
__global__ __launch_bounds__(256)
void build_map_kernel(const int* __restrict__ ys) {
    const int b = blockIdx.x;
    const int tid = threadIdx.x;
    for (int i = tid; i < VV; i += 256)
        g_colidx[(size_t)b * VV + i] = UNUSED_SENT;
    __syncthreads();
    int col = 0;
    if (tid < GG) {
        if (tid > 0) {
            int y = ys[b * LL + tid - 1];
            col = y < 0 ? 0 : y;
        }
        atomicMin(&g_colidx[(size_t)b * VV + col], tid);
    }
    __syncthreads();
    if (tid < GG)
        g_us[b * GG + tid] = g_colidx[(size_t)b * VV + col];
}

// ---------------------------------------------------------------------------
// Main GEMM (bf16 mma.sync, 4 warps, 128x128) over COMPACT rows, with fused
// LSE partials + selected-logit scatter. Tiles past g_live exit.
// ---------------------------------------------------------------------------
__global__ __launch_bounds__(128, 2)
void gemm_lse_kernel(const float* __restrict__ bias) {
    const int by = blockIdx.y;
    const int row0 = by * BM;
    if (row0 >= g_live) return;

    extern __shared__ char dsm[];
    __shared__ float2 red[2][BM];

    const int tid = threadIdx.x;
    const int warp = tid >> 5, lane = tid & 31;
    const int wm = (warp & 1) * 64, wn = (warp >> 1) * 64;
    const int bx = blockIdx.x;
    const int col0 = bx * BN;
    const uint32_t sbase = smem_u32(dsm);

    const __nv_bfloat16* srcA = g_hsb + ((size_t)row0 + tid) * EE;
    const __nv_bfloat16* srcB = g_Wtb + ((size_t)col0 + tid) * EE;
    uint32_t dsw[4];
#pragma unroll
    for (int c = 0; c < 4; c++) dsw[c] = swz(tid, c);

    float acc[4][8][4];
#pragma unroll
    for (int mi = 0; mi < 4; mi++)
#pragma unroll
        for (int ni = 0; ni < 8; ni++)
#pragma unroll
            for (int r = 0; r < 4; r++) acc[mi][ni][r] = 0.f;

    uint32_t aoff[2][4], boff[2][4];
#pragma unroll
    for (int kk = 0; kk < 2; kk++) {
#pragma unroll
        for (int mi = 0; mi < 4; mi++) {
            int r = wm + mi * 16 + (lane & 15);
            int c = kk * 2 + (lane >> 4);
            aoff[kk][mi] = sbase + swz(r, c);
        }
#pragma unroll
        for (int nj = 0; nj < 4; nj++) {
            int r = wn + nj * 16 + ((lane >> 4) << 3) + (lane & 7);
            int c = kk * 2 + ((lane >> 3) & 1);
            boff[kk][nj] = sbase + 8192 + swz(r, c);
        }
    }

#define LOAD_STAGE(st, kt) do { \
    uint32_t b_ = (uint32_t)(st) * 16384; \
    const __nv_bfloat16* a_ = srcA + (kt) * BK; \
    const __nv_bfloat16* w_ = srcB + (kt) * BK; \
    cp16(sbase + b_ + dsw[0], a_); \
    cp16(sbase + b_ + dsw[1], a_ + 8); \
    cp16(sbase + b_ + dsw[2], a_ + 16); \
    cp16(sbase + b_ + dsw[3], a_ + 24); \
    cp16(sbase + b_ + 8192 + dsw[0], w_); \
    cp16(sbase + b_ + 8192 + dsw[1], w_ + 8); \
    cp16(sbase + b_ + 8192 + dsw[2], w_ + 16); \
    cp16(sbase + b_ + 8192 + dsw[3], w_ + 24); \
    asm volatile("cp.async.commit_group;" ::: "memory"); \
} while (0)

    LOAD_STAGE(0, 0);
    LOAD_STAGE(1, 1);
    LOAD_STAGE(2, 2);

    for (int kt = 0; kt < KITERS; kt++) {
        const int st = kt & 3;
        if (kt < KITERS - 2)
            asm volatile("cp.async.wait_group 2;" ::: "memory");
        else if (kt == KITERS - 2)
            asm volatile("cp.async.wait_group 1;" ::: "memory");
        else
            asm volatile("cp.async.wait_group 0;" ::: "memory");
        __syncthreads();

        const uint32_t stb = (uint32_t)st * 16384;
#pragma unroll
        for (int kk = 0; kk < 2; kk++) {
            uint32_t af[4][4], bf[4][4];
#pragma unroll
            for (int mi = 0; mi < 4; mi++)
                asm volatile("ldmatrix.sync.aligned.m8n8.x4.shared.b16 {%0,%1,%2,%3}, [%4];"
                             : "=r"(af[mi][0]), "=r"(af[mi][1]), "=r"(af[mi][2]), "=r"(af[mi][3])
                             : "r"(aoff[kk][mi] + stb));
#pragma unroll
            for (int nj = 0; nj < 4; nj++)
                asm volatile("ldmatrix.sync.aligned.m8n8.x4.shared.b16 {%0,%1,%2,%3}, [%4];"
                             : "=r"(bf[nj][0]), "=r"(bf[nj][1]), "=r"(bf[nj][2]), "=r"(bf[nj][3])
                             : "r"(boff[kk][nj] + stb));
#pragma unroll
            for (int mi = 0; mi < 4; mi++)
#pragma unroll
                for (int ni = 0; ni < 8; ni++)
                    asm volatile(
                        "mma.sync.aligned.m16n8k16.row.col.f32.bf16.bf16.f32 "
                        "{%0,%1,%2,%3}, {%4,%5,%6,%7}, {%8,%9}, {%0,%1,%2,%3};"
                        : "+f"(acc[mi][ni][0]), "+f"(acc[mi][ni][1]),
                          "+f"(acc[mi][ni][2]), "+f"(acc[mi][ni][3])
                        : "r"(af[mi][0]), "r"(af[mi][1]), "r"(af[mi][2]), "r"(af[mi][3]),
                          "r"(bf[ni >> 1][(ni & 1) * 2]), "r"(bf[ni >> 1][(ni & 1) * 2 + 1]));
        }
        if (kt + 3 < KITERS) LOAD_STAGE((kt + 3) & 3, kt + 3);
    }
#undef LOAD_STAGE

    // Epilogue: bias add, selected-logit scatter, LSE partials (max then sum)
#pragma unroll
    for (int mi = 0; mi < 4; mi++) {
        const int r1 = row0 + wm + mi * 16 + (lane >> 2);
        const int r2 = r1 + 8;
        const int b1 = g_rowb[r1];
        const int b2 = g_rowb[r2];
        float vv1[16], vv2[16];
#pragma unroll
        for (int ni = 0; ni < 8; ni++) {
            int gcol = col0 + wn + ni * 8 + 2 * (lane & 3);
            bool ok = gcol < VV;
            float b0 = 0.f, bb = 0.f;
            if (ok) { float2 bv = *(const float2*)(bias + gcol); b0 = bv.x; bb = bv.y; }
            float a0 = acc[mi][ni][0] + b0, a1 = acc[mi][ni][1] + bb;
            float a2 = acc[mi][ni][2] + b0, a3 = acc[mi][ni][3] + bb;
            vv1[2 * ni] = ok ? a0 : NEGF; vv1[2 * ni + 1] = ok ? a1 : NEGF;
            vv2[2 * ni] = ok ? a2 : NEGF; vv2[2 * ni + 1] = ok ? a3 : NEGF;
            if (ok && b1 >= 0) {
                int u0 = g_colidx[(size_t)b1 * VV + gcol];
                int u1 = g_colidx[(size_t)b1 * VV + gcol + 1];
                if (u0 < GG) g_sel[(size_t)r1 * SELP + u0] = a0;
                if (u1 < GG) g_sel[(size_t)r1 * SELP + u1] = a1;
            }
            if (ok && b2 >= 0) {
                int u0 = g_colidx[(size_t)b2 * VV + gcol];
                int u1 = g_colidx[(size_t)b2 * VV + gcol + 1];
                if (u0 < GG) g_sel[(size_t)r2 * SELP + u0] = a2;
                if (u1 < GG) g_sel[(size_t)r2 * SELP + u1] = a3;
            }
        }
        float m1 = vv1[0], m2 = vv2[0];
#pragma unroll
        for (int j = 1; j < 16; j++) { m1 = fmaxf(m1, vv1[j]); m2 = fmaxf(m2, vv2[j]); }
        float s1 = 0.f, s2 = 0.f;
#pragma unroll
        for (int j = 0; j < 16; j++) { s1 += __expf(vv1[j] - m1); s2 += __expf(vv2[j] - m2); }

#pragma unroll
        for (int msk = 1; msk <= 2; msk <<= 1) {
            float om = __shfl_xor_sync(0xffffffffu, m1, msk);
            float os = __shfl_xor_sync(0xffffffffu, s1, msk);
            float M = fmaxf(m1, om);
            s1 = s1 * __expf(m1 - M) + os * __expf(om - M);
            m1 = M;
            om = __shfl_xor_sync(0xffffffffu, m2, msk);
            os = __shfl_xor_sync(0xffffffffu, s2, msk);
            M = fmaxf(m2, om);
            s2 = s2 * __expf(m2 - M) + os * __expf(om - M);
            m2 = M;
        }
        if ((lane & 3) == 0) {
            int rr = wm + mi * 16 + (lane >> 2);
            red[warp >> 1][rr] = make_float2(m1, s1);
            red[warp >> 1][rr + 8] = make_float2(m2, s2);
        }
    }
    __syncthreads();
    {
        float2 p0 = red[0][tid];
        float2 p1 = red[1][tid];
        float M = fmaxf(p0.x, p1.x);
        float s = p0.y * __expf(p0.x - M) + p1.y * __expf(p1.x - M);
        int grow = row0 + tid;
        if (grow < MM) g_part[(size_t)grow * NTILES + bx] = make_float2(M, s);
    }
}

// ---------------------------------------------------------------------------
// Combine (compact rows): lse reduce + lp[o][s] = sel[o][us[s]] - lse
// ---------------------------------------------------------------------------
__global__ __launch_bounds__(128)
void combine_kernel() {
    const int o = blockIdx.x;
    const int b = g_rowb[o];
    if (b < 0) return;

    __shared__ float s_lse;
    const int tid = threadIdx.x;
    if (tid < 32) {
        float2 p = g_part[(size_t)o * NTILES + tid];
        float m = p.x, s = p.y;
#pragma unroll
        for (int msk = 16; msk > 0; msk >>= 1) {
            float om = __shfl_xor_sync(0xffffffffu, m, msk);
            float os = __shfl_xor_sync(0xffffffffu, s, msk);
            float M = fmaxf(m, om);
            s = s * __expf(m - M) + os * __expf(om - M);
            m = M;
        }
        if (tid == 0) s_lse = m + logf(s);
    }
    __syncthreads();
    if (tid >= GG) return;
    int u = g_us[b * GG + tid];
    g_lp[(size_t)o * GG + tid] = g_sel[(size_t)o * SELP + u] - s_lse;
}

// ---------------------------------------------------------------------------
// CTC forward DP, one block per batch element (compact lp rows)
// ---------------------------------------------------------------------------
__global__ __launch_bounds__(256)
void ctc_dp_kernel(const int* __restrict__ ys, const int* __restrict__ ilens,
                   const int* __restrict__ olens) {
    extern __shared__ float sm[];
    float* lps = sm;                     // [<=TT][GG]
    float* abuf = sm + TT * GG;          // [2][256]

    const int b = blockIdx.x;
    const int tid = threadIdx.x;
    const int s = tid;
    const int ilen = ilens[b];

    const float* src = g_lp + (size_t)g_base[b] * GG;
    for (int i = tid; i < ilen * GG; i += blockDim.x) lps[i] = src[i];

    int g = 0;
    bool allow = false;
    if (s < SS && (s & 1)) {
        int l = s >> 1;
        g = 1 + l;
        int yr = ys[b * LL + l];
        int y = yr < 0 ? 0 : yr;
        int ypr = -1;
        if (l > 0) {
            int yp = ys[b * LL + l - 1];
            ypr = yp < 0 ? 0 : yp;
        }
        allow = (y != 0) && (y != ypr);
    }

    float* a0 = abuf;
    float* a1 = abuf + 256;
    a0[s] = (s == 0) ? lps[0] : ((s == 1) ? lps[1] : NEGF);
    __syncthreads();

    for (int t = 1; t < ilen; t++) {
        if (s < SS) {
            float v1 = a0[s];
            float v2 = (s >= 1) ? a0[s - 1] : NEGF;
            float v3 = (s >= 2 && allow) ? a0[s - 2] : NEGF;
            float m = fmaxf(v1, fmaxf(v2, v3));
            float sum = __expf(v1 - m) + __expf(v2 - m) + __expf(v3 - m);
            a1[s] = m + __logf(sum) + lps[t * GG + g];
        }
        __syncthreads();
        float* tmp = a0; a0 = a1; a1 = tmp;
    }

    if (tid == 0) {
        const int olen = olens[b];
        float va = a0[2 * olen];
        float vb = a0[2 * olen - 1];
        float m = fmaxf(va, vb);
        g_ll[b] = m + logf(expf(va - m) + expf(vb - m));
    }
}

__global__ void finalize_kernel(float* __restrict__ out) {
    if (threadIdx.x == 0) {
        float sum = 0.0f;
        for (int i = 0; i < BSZ; i++) sum += g_ll[i];
        out[0] = -sum / (float)BSZ;
    }
}

// ---------------------------------------------------------------------------
extern "C" void kernel_launch(void* const* d_in, const int* in_sizes, int n_in,
                              void* d_out, int out_size) {
    const float* hs    = (const float*)d_in[0];
    const float* W     = (const float*)d_in[1];
    const float* bias  = (const float*)d_in[2];
    const int*   ys    = (const int*)d_in[3];
    const int*   ilens = (const int*)d_in[4];
    const int*   olens = (const int*)d_in[5];
    float* out = (float*)d_out;

    prefix_kernel<<<1, 32>>>(ilens);
    rowmap_init_kernel<<<(MPAD + 255) / 256, 256>>>();
    rowmap_build_kernel<<<(MM + 255) / 256, 256>>>(ilens);

    conv_hs_kernel<<<(MPAD * EE) / 1024, 256>>>(hs);
    conv_W_kernel<<<dim3(VV / 32, EE / 32), dim3(32, 8)>>>(W);
    pad_W_kernel<<<((NPAD - VV) * EE + 255) / 256, 256>>>();
    build_map_kernel<<<BSZ, 256>>>(ys);

    const int gemm_smem = NST * 16384;   // 64 KB
    cudaFuncSetAttribute(gemm_lse_kernel,
                         cudaFuncAttributeMaxDynamicSharedMemorySize, gemm_smem);
    dim3 ggrid(NPAD / BN, MPAD / BM);    // 32 x 63
    gemm_lse_kernel<<<ggrid, 128, gemm_smem>>>(bias);

    combine_kernel<<<MM, 128>>>();

    const int dp_smem = TT * GG * sizeof(float) + 2 * 256 * sizeof(float);
    cudaFuncSetAttribute(ctc_dp_kernel,
                         cudaFuncAttributeMaxDynamicSharedMemorySize, dp_smem);
    ctc_dp_kernel<<<BSZ, 256, dp_smem>>>(ys, ilens, olens);

    finalize_kernel<<<1, 32>>>(out);
}

// round 9
// speedup vs baseline: 2.0413x; 1.0275x over previous
#include <cuda_runtime.h>
#include <cuda_bf16.h>
#include <math.h>
#include <stdint.h>

// Problem constants
#define BSZ 16
#define TT  500
#define EE  1024
#define VV  4000
#define LL  100
#define SS  201
#define GG  101
#define MM  (BSZ*TT)     // 8000
#define MPAD 8064        // 63*128
#define NPAD 4096        // 32*128
#define NEGF (-1e30f)
#define SELP 112
#define UNUSED_SENT 0x7fffffff

// GEMM tiling (4 warps, warp tile 64x64)
#define BM 128
#define BN 128
#define BK 32
#define NST 4
#define KITERS (EE/BK)   // 32
#define NTILES (NPAD/BN) // 32

// Scratch (device globals: allocation-free per harness rules)
__device__ __nv_bfloat16 g_hsb[(size_t)MPAD * EE];   // COMPACT rows; dead rows zero
__device__ __nv_bfloat16 g_Wtb[(size_t)NPAD * EE];
__device__ int g_colidx[(size_t)BSZ * VV];           // col -> unique state idx (sentinel unused)
__device__ int g_us[BSZ * GG];
__device__ int g_base[BSZ + 1];
__device__ int g_live;
__device__ int g_rowsrc[MPAD];                       // compact row -> original row (-1 dead)
__device__ int g_rowb[MPAD];                         // compact row -> batch (-1 dead)
__device__ float2 g_part[(size_t)MM * NTILES];
__device__ float g_sel[(size_t)MM * SELP];
__device__ float g_lp[(size_t)MM * GG];              // compact-row indexed
__device__ float g_ll[BSZ];

// ---------------------------------------------------------------------------
__device__ __forceinline__ uint32_t smem_u32(const void* p) {
    uint32_t a;
    asm("{ .reg .u64 t; cvta.to.shared.u64 t, %1; cvt.u32.u64 %0, t; }" : "=r"(a) : "l"(p));
    return a;
}
__device__ __forceinline__ void cp16(uint32_t dst, const void* src) {
    asm volatile("cp.async.cg.shared.global [%0], [%1], 16;" :: "r"(dst), "l"(src));
}
__device__ __forceinline__ uint32_t swz(int row, int c) {
    return (uint32_t)(row * 64 + ((c ^ ((row >> 1) & 3)) << 4));
}

// ---------------------------------------------------------------------------
// Setup: block 0 = prefix + row maps; blocks 1..16 = per-batch column maps
// ---------------------------------------------------------------------------
__global__ __launch_bounds__(256)
void setup_kernel(const int* __restrict__ ilens, const int* __restrict__ ys) {
    const int tid = threadIdx.x;
    if (blockIdx.x == 0) {
        if (tid == 0) {
            int acc = 0;
            for (int b = 0; b < BSZ; b++) { g_base[b] = acc; acc += ilens[b]; }
            g_base[BSZ] = acc;
            g_live = acc;
        }
        __syncthreads();
        for (int i = tid; i < MPAD; i += 256) { g_rowsrc[i] = -1; g_rowb[i] = -1; }
        __syncthreads();
        for (int row = tid; row < MM; row += 256) {
            int b = row / TT, t = row % TT;
            if (t < ilens[b]) {
                int o = g_base[b] + t;
                g_rowsrc[o] = row;
                g_rowb[o] = b;
            }
        }
    } else {
        const int b = blockIdx.x - 1;
        for (int i = tid; i < VV; i += 256)
            g_colidx[(size_t)b * VV + i] = UNUSED_SENT;
        __syncthreads();
        int col = 0;
        if (tid < GG) {
            if (tid > 0) {
                int y = ys[b * LL + tid - 1];
                col = y < 0 ? 0 : y;
            }
            atomicMin(&g_colidx[(size_t)b * VV + col], tid);
        }
        __syncthreads();
        if (tid < GG)
            g_us[b * GG + tid] = g_colidx[(size_t)b * VV + col];
    }
}

// ---------------------------------------------------------------------------
// Conversion kernels
// ---------------------------------------------------------------------------
__global__ __launch_bounds__(256)
void conv_hs_kernel(const float* __restrict__ hs) {
    size_t i = ((size_t)blockIdx.x * 256 + threadIdx.x) * 4;
    if (i >= (size_t)MPAD * EE) return;
    int orow = (int)(i >> 10);
    int k = (int)(i & 1023);
    int src = g_rowsrc[orow];
    float4 v = make_float4(0.f, 0.f, 0.f, 0.f);
    if (src >= 0) v = *(const float4*)(hs + (size_t)src * EE + k);
    __nv_bfloat162* dst = (__nv_bfloat162*)(g_hsb + i);
    dst[0] = __nv_bfloat162(__float2bfloat16(v.x), __float2bfloat16(v.y));
    dst[1] = __nv_bfloat162(__float2bfloat16(v.z), __float2bfloat16(v.w));
}

// W transpose+convert; blocks with n0 >= VV write zero padding rows.
__global__ __launch_bounds__(256)
void conv_W_kernel(const float* __restrict__ W) {
    __shared__ float t[32][33];
    int n0 = blockIdx.x * 32;
    int k0 = blockIdx.y * 32;
    int tx = threadIdx.x;
    int ty = threadIdx.y;
    if (n0 >= VV) {
#pragma unroll
        for (int j = 0; j < 32; j += 8)
            g_Wtb[(size_t)(n0 + ty + j) * EE + k0 + tx] = __float2bfloat16(0.f);
        return;
    }
#pragma unroll
    for (int j = 0; j < 32; j += 8)
        t[ty + j][tx] = W[(size_t)(k0 + ty + j) * VV + n0 + tx];
    __syncthreads();
#pragma unroll
    for (int j = 0; j < 32; j += 8)
        g_Wtb[(size_t)(n0 + ty + j) * EE + k0 + tx] = __float2bfloat16(t[tx][ty + j]);
}

// ---------------------------------------------------------------------------
// Main GEMM (bf16 mma.sync, 4 warps, 128x128) over COMPACT rows, with fused
// LSE partials + selected-logit scatter (smem-staged column map).
// ---------------------------------------------------------------------------
__global__ __launch_bounds__(128, 2)
void gemm_lse_kernel(const float* __restrict__ bias) {
    const int by = blockIdx.y;
    const int row0 = by * BM;
    if (row0 >= g_live) return;

    extern __shared__ char dsm[];
    __shared__ float2 red[2][BM];
    __shared__ int scol[2][BM];

    const int tid = threadIdx.x;
    const int warp = tid >> 5, lane = tid & 31;
    const int wm = (warp & 1) * 64, wn = (warp >> 1) * 64;
    const int bx = blockIdx.x;
    const int col0 = bx * BN;
    const uint32_t sbase = smem_u32(dsm);

    const __nv_bfloat16* srcA = g_hsb + ((size_t)row0 + tid) * EE;
    const __nv_bfloat16* srcB = g_Wtb + ((size_t)col0 + tid) * EE;
    uint32_t dsw[4];
#pragma unroll
    for (int c = 0; c < 4; c++) dsw[c] = swz(tid, c);

    // Stage per-batch column maps for this tile's rows (<=2 batches).
    const int b_lo = g_rowb[row0];
    const int lastrow = (row0 + BM - 1 < g_live) ? row0 + BM - 1 : g_live - 1;
    const int b_hi = g_rowb[lastrow];
    {
        int gc = col0 + tid;
        bool okc = gc < VV;
        scol[0][tid] = okc ? g_colidx[(size_t)b_lo * VV + gc] : UNUSED_SENT;
        scol[1][tid] = (okc && b_hi >= 0) ? g_colidx[(size_t)b_hi * VV + gc] : UNUSED_SENT;
    }

    float acc[4][8][4];
#pragma unroll
    for (int mi = 0; mi < 4; mi++)
#pragma unroll
        for (int ni = 0; ni < 8; ni++)
#pragma unroll
            for (int r = 0; r < 4; r++) acc[mi][ni][r] = 0.f;

    uint32_t aoff[2][4], boff[2][4];
#pragma unroll
    for (int kk = 0; kk < 2; kk++) {
#pragma unroll
        for (int mi = 0; mi < 4; mi++) {
            int r = wm + mi * 16 + (lane & 15);
            int c = kk * 2 + (lane >> 4);
            aoff[kk][mi] = sbase + swz(r, c);
        }
#pragma unroll
        for (int nj = 0; nj < 4; nj++) {
            int r = wn + nj * 16 + ((lane >> 4) << 3) + (lane & 7);
            int c = kk * 2 + ((lane >> 3) & 1);
            boff[kk][nj] = sbase + 8192 + swz(r, c);
        }
    }

#define LOAD_STAGE(st, kt) do { \
    uint32_t b_ = (uint32_t)(st) * 16384; \
    const __nv_bfloat16* a_ = srcA + (kt) * BK; \
    const __nv_bfloat16* w_ = srcB + (kt) * BK; \
    cp16(sbase + b_ + dsw[0], a_); \
    cp16(sbase + b_ + dsw[1], a_ + 8); \
    cp16(sbase + b_ + dsw[2], a_ + 16); \
    cp16(sbase + b_ + dsw[3], a_ + 24); \
    cp16(sbase + b_ + 8192 + dsw[0], w_); \
    cp16(sbase + b_ + 8192 + dsw[1], w_ + 8); \
    cp16(sbase + b_ + 8192 + dsw[2], w_ + 16); \
    cp16(sbase + b_ + 8192 + dsw[3], w_ + 24); \
    asm volatile("cp.async.commit_group;" ::: "memory"); \
} while (0)

    LOAD_STAGE(0, 0);
    LOAD_STAGE(1, 1);
    LOAD_STAGE(2, 2);

    for (int kt = 0; kt < KITERS; kt++) {
        const int st = kt & 3;
        if (kt < KITERS - 2)
            asm volatile("cp.async.wait_group 2;" ::: "memory");
        else if (kt == KITERS - 2)
            asm volatile("cp.async.wait_group 1;" ::: "memory");
        else
            asm volatile("cp.async.wait_group 0;" ::: "memory");
        __syncthreads();

        const uint32_t stb = (uint32_t)st * 16384;
#pragma unroll
        for (int kk = 0; kk < 2; kk++) {
            uint32_t af[4][4], bf[4][4];
#pragma unroll
            for (int mi = 0; mi < 4; mi++)
                asm volatile("ldmatrix.sync.aligned.m8n8.x4.shared.b16 {%0,%1,%2,%3}, [%4];"
                             : "=r"(af[mi][0]), "=r"(af[mi][1]), "=r"(af[mi][2]), "=r"(af[mi][3])
                             : "r"(aoff[kk][mi] + stb));
#pragma unroll
            for (int nj = 0; nj < 4; nj++)
                asm volatile("ldmatrix.sync.aligned.m8n8.x4.shared.b16 {%0,%1,%2,%3}, [%4];"
                             : "=r"(bf[nj][0]), "=r"(bf[nj][1]), "=r"(bf[nj][2]), "=r"(bf[nj][3])
                             : "r"(boff[kk][nj] + stb));
#pragma unroll
            for (int mi = 0; mi < 4; mi++)
#pragma unroll
                for (int ni = 0; ni < 8; ni++)
                    asm volatile(
                        "mma.sync.aligned.m16n8k16.row.col.f32.bf16.bf16.f32 "
                        "{%0,%1,%2,%3}, {%4,%5,%6,%7}, {%8,%9}, {%0,%1,%2,%3};"
                        : "+f"(acc[mi][ni][0]), "+f"(acc[mi][ni][1]),
                          "+f"(acc[mi][ni][2]), "+f"(acc[mi][ni][3])
                        : "r"(af[mi][0]), "r"(af[mi][1]), "r"(af[mi][2]), "r"(af[mi][3]),
                          "r"(bf[ni >> 1][(ni & 1) * 2]), "r"(bf[ni >> 1][(ni & 1) * 2 + 1]));
        }
        if (kt + 3 < KITERS) LOAD_STAGE((kt + 3) & 3, kt + 3);
    }
#undef LOAD_STAGE

    // Epilogue: bias add, selected-logit scatter (smem map), LSE partials
#pragma unroll
    for (int mi = 0; mi < 4; mi++) {
        const int r1 = row0 + wm + mi * 16 + (lane >> 2);
        const int r2 = r1 + 8;
        const int b1 = g_rowb[r1];
        const int b2 = g_rowb[r2];
        const int* c1 = (b1 == b_lo) ? scol[0] : scol[1];
        const int* c2 = (b2 == b_lo) ? scol[0] : scol[1];
        float vv1[16], vv2[16];
#pragma unroll
        for (int ni = 0; ni < 8; ni++) {
            int lc = wn + ni * 8 + 2 * (lane & 3);
            int gcol = col0 + lc;
            bool ok = gcol < VV;
            float b0 = 0.f, bb = 0.f;
            if (ok) { float2 bv = *(const float2*)(bias + gcol); b0 = bv.x; bb = bv.y; }
            float a0 = acc[mi][ni][0] + b0, a1 = acc[mi][ni][1] + bb;
            float a2 = acc[mi][ni][2] + b0, a3 = acc[mi][ni][3] + bb;
            vv1[2 * ni] = ok ? a0 : NEGF; vv1[2 * ni + 1] = ok ? a1 : NEGF;
            vv2[2 * ni] = ok ? a2 : NEGF; vv2[2 * ni + 1] = ok ? a3 : NEGF;
            if (b1 >= 0) {
                int u0 = c1[lc], u1 = c1[lc + 1];
                if (u0 < GG) g_sel[(size_t)r1 * SELP + u0] = a0;
                if (u1 < GG) g_sel[(size_t)r1 * SELP + u1] = a1;
            }
            if (b2 >= 0) {
                int u0 = c2[lc], u1 = c2[lc + 1];
                if (u0 < GG) g_sel[(size_t)r2 * SELP + u0] = a2;
                if (u1 < GG) g_sel[(size_t)r2 * SELP + u1] = a3;
            }
        }
        float m1 = vv1[0], m2 = vv2[0];
#pragma unroll
        for (int j = 1; j < 16; j++) { m1 = fmaxf(m1, vv1[j]); m2 = fmaxf(m2, vv2[j]); }
        float s1 = 0.f, s2 = 0.f;
#pragma unroll
        for (int j = 0; j < 16; j++) { s1 += __expf(vv1[j] - m1); s2 += __expf(vv2[j] - m2); }

#pragma unroll
        for (int msk = 1; msk <= 2; msk <<= 1) {
            float om = __shfl_xor_sync(0xffffffffu, m1, msk);
            float os = __shfl_xor_sync(0xffffffffu, s1, msk);
            float M = fmaxf(m1, om);
            s1 = s1 * __expf(m1 - M) + os * __expf(om - M);
            m1 = M;
            om = __shfl_xor_sync(0xffffffffu, m2, msk);
            os = __shfl_xor_sync(0xffffffffu, s2, msk);
            M = fmaxf(m2, om);
            s2 = s2 * __expf(m2 - M) + os * __expf(om - M);
            m2 = M;
        }
        if ((lane & 3) == 0) {
            int rr = wm + mi * 16 + (lane >> 2);
            red[warp >> 1][rr] = make_float2(m1, s1);
            red[warp >> 1][rr + 8] = make_float2(m2, s2);
        }
    }
    __syncthreads();
    {
        float2 p0 = red[0][tid];
        float2 p1 = red[1][tid];
        float M = fmaxf(p0.x, p1.x);
        float s = p0.y * __expf(p0.x - M) + p1.y * __expf(p1.x - M);
        int grow = row0 + tid;
        if (grow < MM) g_part[(size_t)grow * NTILES + bx] = make_float2(M, s);
    }
}

// ---------------------------------------------------------------------------
// Combine (compact rows): lse reduce + lp[o][s] = sel[o][us[s]] - lse
// ---------------------------------------------------------------------------
__global__ __launch_bounds__(128)
void combine_kernel() {
    const int o = blockIdx.x;
    const int b = g_rowb[o];
    if (b < 0) return;

    __shared__ float s_lse;
    const int tid = threadIdx.x;
    if (tid < 32) {
        float2 p = g_part[(size_t)o * NTILES + tid];
        float m = p.x, s = p.y;
#pragma unroll
        for (int msk = 16; msk > 0; msk >>= 1) {
            float om = __shfl_xor_sync(0xffffffffu, m, msk);
            float os = __shfl_xor_sync(0xffffffffu, s, msk);
            float M = fmaxf(m, om);
            s = s * __expf(m - M) + os * __expf(om - M);
            m = M;
        }
        if (tid == 0) s_lse = m + logf(s);
    }
    __syncthreads();
    if (tid >= GG) return;
    int u = g_us[b * GG + tid];
    g_lp[(size_t)o * GG + tid] = g_sel[(size_t)o * SELP + u] - s_lse;
}

// ---------------------------------------------------------------------------
// CTC forward DP, one block per batch element (compact lp rows)
// ---------------------------------------------------------------------------
__global__ __launch_bounds__(256)
void ctc_dp_kernel(const int* __restrict__ ys, const int* __restrict__ ilens,
                   const int* __restrict__ olens) {
    extern __shared__ float sm[];
    float* lps = sm;                     // [<=TT][GG]
    float* abuf = sm + TT * GG;          // [2][256]

    const int b = blockIdx.x;
    const int tid = threadIdx.x;
    const int s = tid;
    const int ilen = ilens[b];

    const float* src = g_lp + (size_t)g_base[b] * GG;
    for (int i = tid; i < ilen * GG; i += blockDim.x) lps[i] = src[i];

    int g = 0;
    bool allow = false;
    if (s < SS && (s & 1)) {
        int l = s >> 1;
        g = 1 + l;
        int yr = ys[b * LL + l];
        int y = yr < 0 ? 0 : yr;
        int ypr = -1;
        if (l > 0) {
            int yp = ys[b * LL + l - 1];
            ypr = yp < 0 ? 0 : yp;
        }
        allow = (y != 0) && (y != ypr);
    }

    float* a0 = abuf;
    float* a1 = abuf + 256;
    a0[s] = (s == 0) ? lps[0] : ((s == 1) ? lps[1] : NEGF);
    __syncthreads();

    for (int t = 1; t < ilen; t++) {
        if (s < SS) {
            float v1 = a0[s];
            float v2 = (s >= 1) ? a0[s - 1] : NEGF;
            float v3 = (s >= 2 && allow) ? a0[s - 2] : NEGF;
            float m = fmaxf(v1, fmaxf(v2, v3));
            float sum = __expf(v1 - m) + __expf(v2 - m) + __expf(v3 - m);
            a1[s] = m + __logf(sum) + lps[t * GG + g];
        }
        __syncthreads();
        float* tmp = a0; a0 = a1; a1 = tmp;
    }

    if (tid == 0) {
        const int olen = olens[b];
        float va = a0[2 * olen];
        float vb = a0[2 * olen - 1];
        float m = fmaxf(va, vb);
        g_ll[b] = m + logf(expf(va - m) + expf(vb - m));
    }
}

__global__ void finalize_kernel(float* __restrict__ out) {
    if (threadIdx.x == 0) {
        float sum = 0.0f;
        for (int i = 0; i < BSZ; i++) sum += g_ll[i];
        out[0] = -sum / (float)BSZ;
    }
}

// ---------------------------------------------------------------------------
extern "C" void kernel_launch(void* const* d_in, const int* in_sizes, int n_in,
                              void* d_out, int out_size) {
    const float* hs    = (const float*)d_in[0];
    const float* W     = (const float*)d_in[1];
    const float* bias  = (const float*)d_in[2];
    const int*   ys    = (const int*)d_in[3];
    const int*   ilens = (const int*)d_in[4];
    const int*   olens = (const int*)d_in[5];
    float* out = (float*)d_out;

    setup_kernel<<<1 + BSZ, 256>>>(ilens, ys);                 // launch 1
    conv_hs_kernel<<<(MPAD * EE) / 1024, 256>>>(hs);           // launch 2
    conv_W_kernel<<<dim3(NPAD / 32, EE / 32), dim3(32, 8)>>>(W); // launch 3

    const int gemm_smem = NST * 16384;   // 64 KB
    cudaFuncSetAttribute(gemm_lse_kernel,
                         cudaFuncAttributeMaxDynamicSharedMemorySize, gemm_smem);
    dim3 ggrid(NPAD / BN, MPAD / BM);    // 32 x 63
    gemm_lse_kernel<<<ggrid, 128, gemm_smem>>>(bias);          // launch 4 (profiled)

    combine_kernel<<<MM, 128>>>();                             // launch 5

    const int dp_smem = TT * GG * sizeof(float) + 2 * 256 * sizeof(float);
    cudaFuncSetAttribute(ctc_dp_kernel,
                         cudaFuncAttributeMaxDynamicSharedMemorySize, dp_smem);
    ctc_dp_kernel<<<BSZ, 256, dp_smem>>>(ys, ilens, olens);    // launch 6

    finalize_kernel<<<1, 32>>>(out);                           // launch 7
}

// round 10
// speedup vs baseline: 2.8183x; 1.3806x over previous
#include <cuda_runtime.h>
#include <cuda_bf16.h>
#include <math.h>
#include <stdint.h>

// Problem constants
#define BSZ 16
#define TT  500
#define EE  1024
#define VV  4000
#define LL  100
#define SS  201
#define GG  101
#define MM  (BSZ*TT)     // 8000
#define MPAD 8064        // 63*128
#define NPAD 4096        // 32*128
#define NEGF (-1e30f)
#define SELP 112
#define UNUSED_SENT 0x7fffffff

// GEMM tiling: 8 warps (2M x 4N), warp tile 64x32
#define BM 128
#define BN 128
#define BK 32
#define NST 4
#define KITERS (EE/BK)   // 32
#define NTILES (NPAD/BN) // 32

// Scratch (device globals: allocation-free per harness rules)
__device__ __nv_bfloat16 g_hsb[(size_t)MPAD * EE];   // COMPACT rows; dead rows zero
__device__ __nv_bfloat16 g_Wtb[(size_t)NPAD * EE];
__device__ int g_colidx[(size_t)BSZ * VV];
__device__ int g_us[BSZ * GG];
__device__ int g_base[BSZ + 1];
__device__ int g_live;
__device__ int g_rowsrc[MPAD];
__device__ int g_rowb[MPAD];
__device__ float2 g_part[(size_t)MM * NTILES];
__device__ float g_sel[(size_t)MM * SELP];
__device__ float g_lp[(size_t)MM * GG];
__device__ float g_ll[BSZ];

// ---------------------------------------------------------------------------
__device__ __forceinline__ uint32_t smem_u32(const void* p) {
    uint32_t a;
    asm("{ .reg .u64 t; cvta.to.shared.u64 t, %1; cvt.u32.u64 %0, t; }" : "=r"(a) : "l"(p));
    return a;
}
__device__ __forceinline__ void cp16(uint32_t dst, const void* src) {
    asm volatile("cp.async.cg.shared.global [%0], [%1], 16;" :: "r"(dst), "l"(src));
}
__device__ __forceinline__ uint32_t swz(int row, int c) {
    return (uint32_t)(row * 64 + ((c ^ ((row >> 1) & 3)) << 4));
}

// ---------------------------------------------------------------------------
// Setup: block 0 = prefix + row maps; blocks 1..16 = per-batch column maps
// ---------------------------------------------------------------------------
__global__ __launch_bounds__(256)
void setup_kernel(const int* __restrict__ ilens, const int* __restrict__ ys) {
    const int tid = threadIdx.x;
    if (blockIdx.x == 0) {
        if (tid == 0) {
            int acc = 0;
            for (int b = 0; b < BSZ; b++) { g_base[b] = acc; acc += ilens[b]; }
            g_base[BSZ] = acc;
            g_live = acc;
        }
        __syncthreads();
        for (int i = tid; i < MPAD; i += 256) { g_rowsrc[i] = -1; g_rowb[i] = -1; }
        __syncthreads();
        for (int row = tid; row < MM; row += 256) {
            int b = row / TT, t = row % TT;
            if (t < ilens[b]) {
                int o = g_base[b] + t;
                g_rowsrc[o] = row;
                g_rowb[o] = b;
            }
        }
    } else {
        const int b = blockIdx.x - 1;
        for (int i = tid; i < VV; i += 256)
            g_colidx[(size_t)b * VV + i] = UNUSED_SENT;
        __syncthreads();
        int col = 0;
        if (tid < GG) {
            if (tid > 0) {
                int y = ys[b * LL + tid - 1];
                col = y < 0 ? 0 : y;
            }
            atomicMin(&g_colidx[(size_t)b * VV + col], tid);
        }
        __syncthreads();
        if (tid < GG)
            g_us[b * GG + tid] = g_colidx[(size_t)b * VV + col];
    }
}

// ---------------------------------------------------------------------------
// Conversion kernels
// ---------------------------------------------------------------------------
__global__ __launch_bounds__(256)
void conv_hs_kernel(const float* __restrict__ hs) {
    size_t i = ((size_t)blockIdx.x * 256 + threadIdx.x) * 4;
    if (i >= (size_t)MPAD * EE) return;
    int orow = (int)(i >> 10);
    int k = (int)(i & 1023);
    int src = g_rowsrc[orow];
    float4 v = make_float4(0.f, 0.f, 0.f, 0.f);
    if (src >= 0) v = *(const float4*)(hs + (size_t)src * EE + k);
    __nv_bfloat162* dst = (__nv_bfloat162*)(g_hsb + i);
    dst[0] = __nv_bfloat162(__float2bfloat16(v.x), __float2bfloat16(v.y));
    dst[1] = __nv_bfloat162(__float2bfloat16(v.z), __float2bfloat16(v.w));
}

__global__ __launch_bounds__(256)
void conv_W_kernel(const float* __restrict__ W) {
    __shared__ float t[32][33];
    int n0 = blockIdx.x * 32;
    int k0 = blockIdx.y * 32;
    int tx = threadIdx.x;
    int ty = threadIdx.y;
    if (n0 >= VV) {
#pragma unroll
        for (int j = 0; j < 32; j += 8)
            g_Wtb[(size_t)(n0 + ty + j) * EE + k0 + tx] = __float2bfloat16(0.f);
        return;
    }
#pragma unroll
    for (int j = 0; j < 32; j += 8)
        t[ty + j][tx] = W[(size_t)(k0 + ty + j) * VV + n0 + tx];
    __syncthreads();
#pragma unroll
    for (int j = 0; j < 32; j += 8)
        g_Wtb[(size_t)(n0 + ty + j) * EE + k0 + tx] = __float2bfloat16(t[tx][ty + j]);
}

// ---------------------------------------------------------------------------
// Main GEMM: 256 threads, 8 warps (2Mx4N), warp tile 64x32, fused LSE +
// selected-logit scatter (smem-staged column map). Compact rows.
// ---------------------------------------------------------------------------
__global__ __launch_bounds__(256, 2)
void gemm_lse_kernel(const float* __restrict__ bias) {
    const int by = blockIdx.y;
    const int row0 = by * BM;
    if (row0 >= g_live) return;

    extern __shared__ char dsm[];
    __shared__ float2 red[4][BM];
    __shared__ int scol[2][BM];

    const int tid = threadIdx.x;
    const int warp = tid >> 5, lane = tid & 31;
    const int wm = (warp & 1) * 64, wn = (warp >> 1) * 32;
    const int bx = blockIdx.x;
    const int col0 = bx * BN;
    const uint32_t sbase = smem_u32(dsm);

    // per-thread cp.async assignment: row = tid/2, two 16B chunks
    const int lrow = tid >> 1;
    const int lc0 = (tid & 1) * 2;
    const uint32_t dA0 = swz(lrow, lc0);
    const uint32_t dA1 = swz(lrow, lc0 + 1);
    const __nv_bfloat16* srcA = g_hsb + ((size_t)row0 + lrow) * EE + lc0 * 8;
    const __nv_bfloat16* srcB = g_Wtb + ((size_t)col0 + lrow) * EE + lc0 * 8;

    // Stage per-batch column maps for this tile's rows (<=2 batches).
    const int b_lo = g_rowb[row0];
    const int lastrow = (row0 + BM - 1 < g_live) ? row0 + BM - 1 : g_live - 1;
    const int b_hi = g_rowb[lastrow];
    if (tid < BM) {
        int gc = col0 + tid;
        bool okc = gc < VV;
        scol[0][tid] = okc ? g_colidx[(size_t)b_lo * VV + gc] : UNUSED_SENT;
        scol[1][tid] = (okc && b_hi >= 0) ? g_colidx[(size_t)b_hi * VV + gc] : UNUSED_SENT;
    }

    float acc[4][4][4];
#pragma unroll
    for (int mi = 0; mi < 4; mi++)
#pragma unroll
        for (int ni = 0; ni < 4; ni++)
#pragma unroll
            for (int r = 0; r < 4; r++) acc[mi][ni][r] = 0.f;

    uint32_t aoff[2][4], boff[2][4];
#pragma unroll
    for (int kk = 0; kk < 2; kk++) {
#pragma unroll
        for (int mi = 0; mi < 4; mi++) {
            int r = wm + mi * 16 + (lane & 15);
            int c = kk * 2 + ((lane >> 4) & 1);
            aoff[kk][mi] = sbase + swz(r, c);
        }
#pragma unroll
        for (int ni = 0; ni < 4; ni++) {
            int r = wn + ni * 8 + (lane & 7);
            int c = kk * 2 + ((lane >> 3) & 1);
            boff[kk][ni] = sbase + 8192 + swz(r, c);
        }
    }

#define LOAD_STAGE(st, kt) do { \
    uint32_t b_ = (uint32_t)(st) * 16384; \
    const __nv_bfloat16* a_ = srcA + (kt) * BK; \
    const __nv_bfloat16* w_ = srcB + (kt) * BK; \
    cp16(sbase + b_ + dA0, a_); \
    cp16(sbase + b_ + dA1, a_ + 8); \
    cp16(sbase + b_ + 8192 + dA0, w_); \
    cp16(sbase + b_ + 8192 + dA1, w_ + 8); \
    asm volatile("cp.async.commit_group;" ::: "memory"); \
} while (0)

    LOAD_STAGE(0, 0);
    LOAD_STAGE(1, 1);
    LOAD_STAGE(2, 2);

    for (int kt = 0; kt < KITERS; kt++) {
        const int st = kt & 3;
        if (kt < KITERS - 2)
            asm volatile("cp.async.wait_group 2;" ::: "memory");
        else if (kt == KITERS - 2)
            asm volatile("cp.async.wait_group 1;" ::: "memory");
        else
            asm volatile("cp.async.wait_group 0;" ::: "memory");
        __syncthreads();

        const uint32_t stb = (uint32_t)st * 16384;
#pragma unroll
        for (int kk = 0; kk < 2; kk++) {
            uint32_t af[4][4], bf[4][2];
#pragma unroll
            for (int mi = 0; mi < 4; mi++)
                asm volatile("ldmatrix.sync.aligned.m8n8.x4.shared.b16 {%0,%1,%2,%3}, [%4];"
                             : "=r"(af[mi][0]), "=r"(af[mi][1]), "=r"(af[mi][2]), "=r"(af[mi][3])
                             : "r"(aoff[kk][mi] + stb));
#pragma unroll
            for (int ni = 0; ni < 4; ni++)
                asm volatile("ldmatrix.sync.aligned.m8n8.x2.shared.b16 {%0,%1}, [%2];"
                             : "=r"(bf[ni][0]), "=r"(bf[ni][1])
                             : "r"(boff[kk][ni] + stb));
#pragma unroll
            for (int mi = 0; mi < 4; mi++)
#pragma unroll
                for (int ni = 0; ni < 4; ni++)
                    asm volatile(
                        "mma.sync.aligned.m16n8k16.row.col.f32.bf16.bf16.f32 "
                        "{%0,%1,%2,%3}, {%4,%5,%6,%7}, {%8,%9}, {%0,%1,%2,%3};"
                        : "+f"(acc[mi][ni][0]), "+f"(acc[mi][ni][1]),
                          "+f"(acc[mi][ni][2]), "+f"(acc[mi][ni][3])
                        : "r"(af[mi][0]), "r"(af[mi][1]), "r"(af[mi][2]), "r"(af[mi][3]),
                          "r"(bf[ni][0]), "r"(bf[ni][1]));
        }
        if (kt + 3 < KITERS) LOAD_STAGE((kt + 3) & 3, kt + 3);
    }
#undef LOAD_STAGE

    // Epilogue: bias add, scatter via smem map, LSE partials (max then sum)
#pragma unroll
    for (int mi = 0; mi < 4; mi++) {
        const int r1 = row0 + wm + mi * 16 + (lane >> 2);
        const int r2 = r1 + 8;
        const int b1 = g_rowb[r1];
        const int b2 = g_rowb[r2];
        const int* c1 = (b1 == b_lo) ? scol[0] : scol[1];
        const int* c2 = (b2 == b_lo) ? scol[0] : scol[1];
        float vv1[8], vv2[8];
#pragma unroll
        for (int ni = 0; ni < 4; ni++) {
            int lc = wn + ni * 8 + 2 * (lane & 3);
            int gcol = col0 + lc;
            bool ok = gcol < VV;
            float b0 = 0.f, bb = 0.f;
            if (ok) { float2 bv = *(const float2*)(bias + gcol); b0 = bv.x; bb = bv.y; }
            float a0 = acc[mi][ni][0] + b0, a1 = acc[mi][ni][1] + bb;
            float a2 = acc[mi][ni][2] + b0, a3 = acc[mi][ni][3] + bb;
            vv1[2 * ni] = ok ? a0 : NEGF; vv1[2 * ni + 1] = ok ? a1 : NEGF;
            vv2[2 * ni] = ok ? a2 : NEGF; vv2[2 * ni + 1] = ok ? a3 : NEGF;
            if (b1 >= 0) {
                int u0 = c1[lc], u1 = c1[lc + 1];
                if (u0 < GG) g_sel[(size_t)r1 * SELP + u0] = a0;
                if (u1 < GG) g_sel[(size_t)r1 * SELP + u1] = a1;
            }
            if (b2 >= 0) {
                int u0 = c2[lc], u1 = c2[lc + 1];
                if (u0 < GG) g_sel[(size_t)r2 * SELP + u0] = a2;
                if (u1 < GG) g_sel[(size_t)r2 * SELP + u1] = a3;
            }
        }
        float m1 = vv1[0], m2 = vv2[0];
#pragma unroll
        for (int j = 1; j < 8; j++) { m1 = fmaxf(m1, vv1[j]); m2 = fmaxf(m2, vv2[j]); }
        float s1 = 0.f, s2 = 0.f;
#pragma unroll
        for (int j = 0; j < 8; j++) { s1 += __expf(vv1[j] - m1); s2 += __expf(vv2[j] - m2); }

#pragma unroll
        for (int msk = 1; msk <= 2; msk <<= 1) {
            float om = __shfl_xor_sync(0xffffffffu, m1, msk);
            float os = __shfl_xor_sync(0xffffffffu, s1, msk);
            float M = fmaxf(m1, om);
            s1 = s1 * __expf(m1 - M) + os * __expf(om - M);
            m1 = M;
            om = __shfl_xor_sync(0xffffffffu, m2, msk);
            os = __shfl_xor_sync(0xffffffffu, s2, msk);
            M = fmaxf(m2, om);
            s2 = s2 * __expf(m2 - M) + os * __expf(om - M);
            m2 = M;
        }
        if ((lane & 3) == 0) {
            int rr = wm + mi * 16 + (lane >> 2);
            red[warp >> 1][rr] = make_float2(m1, s1);
            red[warp >> 1][rr + 8] = make_float2(m2, s2);
        }
    }
    __syncthreads();
    if (tid < BM) {
        float m = NEGF, s = 0.f;
#pragma unroll
        for (int j = 0; j < 4; j++) {
            float2 p = red[j][tid];
            float M = fmaxf(m, p.x);
            s = s * __expf(m - M) + p.y * __expf(p.x - M);
            m = M;
        }
        int grow = row0 + tid;
        if (grow < MM) g_part[(size_t)grow * NTILES + bx] = make_float2(m, s);
    }
}

// ---------------------------------------------------------------------------
// Combine (compact rows): lse reduce + lp[o][s] = sel[o][us[s]] - lse
// ---------------------------------------------------------------------------
__global__ __launch_bounds__(128)
void combine_kernel() {
    const int o = blockIdx.x;
    const int b = g_rowb[o];
    if (b < 0) return;

    __shared__ float s_lse;
    const int tid = threadIdx.x;
    if (tid < 32) {
        float2 p = g_part[(size_t)o * NTILES + tid];
        float m = p.x, s = p.y;
#pragma unroll
        for (int msk = 16; msk > 0; msk >>= 1) {
            float om = __shfl_xor_sync(0xffffffffu, m, msk);
            float os = __shfl_xor_sync(0xffffffffu, s, msk);
            float M = fmaxf(m, om);
            s = s * __expf(m - M) + os * __expf(om - M);
            m = M;
        }
        if (tid == 0) s_lse = m + logf(s);
    }
    __syncthreads();
    if (tid >= GG) return;
    int u = g_us[b * GG + tid];
    g_lp[(size_t)o * GG + tid] = g_sel[(size_t)o * SELP + u] - s_lse;
}

// ---------------------------------------------------------------------------
// CTC forward DP, one block per batch element (compact lp rows)
// ---------------------------------------------------------------------------
__global__ __launch_bounds__(256)
void ctc_dp_kernel(const int* __restrict__ ys, const int* __restrict__ ilens,
                   const int* __restrict__ olens) {
    extern __shared__ float sm[];
    float* lps = sm;                     // [<=TT][GG]
    float* abuf = sm + TT * GG;          // [2][256]

    const int b = blockIdx.x;
    const int tid = threadIdx.x;
    const int s = tid;
    const int ilen = ilens[b];

    const float* src = g_lp + (size_t)g_base[b] * GG;
    for (int i = tid; i < ilen * GG; i += blockDim.x) lps[i] = src[i];

    int g = 0;
    bool allow = false;
    if (s < SS && (s & 1)) {
        int l = s >> 1;
        g = 1 + l;
        int yr = ys[b * LL + l];
        int y = yr < 0 ? 0 : yr;
        int ypr = -1;
        if (l > 0) {
            int yp = ys[b * LL + l - 1];
            ypr = yp < 0 ? 0 : yp;
        }
        allow = (y != 0) && (y != ypr);
    }

    float* a0 = abuf;
    float* a1 = abuf + 256;
    a0[s] = (s == 0) ? lps[0] : ((s == 1) ? lps[1] : NEGF);
    __syncthreads();

    for (int t = 1; t < ilen; t++) {
        if (s < SS) {
            float v1 = a0[s];
            float v2 = (s >= 1) ? a0[s - 1] : NEGF;
            float v3 = (s >= 2 && allow) ? a0[s - 2] : NEGF;
            float m = fmaxf(v1, fmaxf(v2, v3));
            float sum = __expf(v1 - m) + __expf(v2 - m) + __expf(v3 - m);
            a1[s] = m + __logf(sum) + lps[t * GG + g];
        }
        __syncthreads();
        float* tmp = a0; a0 = a1; a1 = tmp;
    }

    if (tid == 0) {
        const int olen = olens[b];
        float va = a0[2 * olen];
        float vb = a0[2 * olen - 1];
        float m = fmaxf(va, vb);
        g_ll[b] = m + logf(expf(va - m) + expf(vb - m));
    }
}

__global__ void finalize_kernel(float* __restrict__ out) {
    if (threadIdx.x == 0) {
        float sum = 0.0f;
        for (int i = 0; i < BSZ; i++) sum += g_ll[i];
        out[0] = -sum / (float)BSZ;
    }
}

// ---------------------------------------------------------------------------
extern "C" void kernel_launch(void* const* d_in, const int* in_sizes, int n_in,
                              void* d_out, int out_size) {
    const float* hs    = (const float*)d_in[0];
    const float* W     = (const float*)d_in[1];
    const float* bias  = (const float*)d_in[2];
    const int*   ys    = (const int*)d_in[3];
    const int*   ilens = (const int*)d_in[4];
    const int*   olens = (const int*)d_in[5];
    float* out = (float*)d_out;

    setup_kernel<<<1 + BSZ, 256>>>(ilens, ys);                   // launch 1
    conv_hs_kernel<<<(MPAD * EE) / 1024, 256>>>(hs);             // launch 2
    conv_W_kernel<<<dim3(NPAD / 32, EE / 32), dim3(32, 8)>>>(W); // launch 3

    const int gemm_smem = NST * 16384;   // 64 KB
    cudaFuncSetAttribute(gemm_lse_kernel,
                         cudaFuncAttributeMaxDynamicSharedMemorySize, gemm_smem);
    dim3 ggrid(NPAD / BN, MPAD / BM);    // 32 x 63
    gemm_lse_kernel<<<ggrid, 256, gemm_smem>>>(bias);            // launch 4 (profiled)

    combine_kernel<<<MM, 128>>>();                               // launch 5

    const int dp_smem = TT * GG * sizeof(float) + 2 * 256 * sizeof(float);
    cudaFuncSetAttribute(ctc_dp_kernel,
                         cudaFuncAttributeMaxDynamicSharedMemorySize, dp_smem);
    ctc_dp_kernel<<<BSZ, 256, dp_smem>>>(ys, ilens, olens);      // launch 6

    finalize_kernel<<<1, 32>>>(out);                             // launch 7
}